// round 9
// baseline (speedup 1.0000x reference)
#include <cuda_runtime.h>
#include <math.h>
#include <stdint.h>

#define NN 10000
#define TT 128
#define HH 128
#define EE 320000
#define NPC 72            // nodes per CTA; 139 * 72 = 10008 >= 10000
#define NCTA 139
#define ROWW 73           // hs row stride in float2 units

// ---------------- device scratch ----------------
__device__ __align__(16) float g_h1[NN * HH];
__device__ __align__(16) float g_xw[NN * HH];
__device__ __align__(16) float g_h2[NN * HH];
__device__ __align__(16) float g_h3[NN * HH];
__device__ __align__(16) float g_deg[NN];
__device__ __align__(16) float g_dinv[NN];
__device__ __align__(16) float g_norm[EE];
__device__ __align__(16) float g_xT[TT * NN];       // transposed input
__device__ __align__(16) float g_Wp2[128 * 512];    // W_hh permuted [k][p], p = jh*4+gate
__device__ __align__(16) float g_wihp[512];         // W_ih permuted  (p = jh*4+gate)
__device__ __align__(16) float g_bp[512];           // b_ih + b_hh permuted

// ---------------- helpers ----------------
__device__ __forceinline__ uint32_t smem_u32(const void* p) {
    uint32_t a;
    asm("{ .reg .u64 t; cvta.to.shared.u64 t, %1; cvt.u32.u64 %0, t; }" : "=r"(a) : "l"(p));
    return a;
}
__device__ __forceinline__ void fma2(unsigned long long& d, unsigned long long a, unsigned long long b) {
    asm("fma.rn.f32x2 %0, %1, %2, %0;" : "+l"(d) : "l"(a), "l"(b));
}
__device__ __forceinline__ void add2(unsigned long long& d, unsigned long long a) {
    asm("add.rn.f32x2 %0, %0, %1;" : "+l"(d) : "l"(a));
}
__device__ __forceinline__ unsigned long long pack2(float x) {
    unsigned long long r;
    asm("mov.b64 %0, {%1, %1};" : "=l"(r) : "f"(x));
    return r;
}
__device__ __forceinline__ float2 unpack2(unsigned long long v) {
    float2 f;
    asm("mov.b64 {%0, %1}, %2;" : "=f"(f.x), "=f"(f.y) : "l"(v));
    return f;
}
__device__ __forceinline__ float ex2f(float x) { float r; asm("ex2.approx.f32 %0, %1;" : "=f"(r) : "f"(x)); return r; }
__device__ __forceinline__ float rcpf(float x) { float r; asm("rcp.approx.f32 %0, %1;" : "=f"(r) : "f"(x)); return r; }
__device__ __forceinline__ float sigf(float x) { return rcpf(1.0f + ex2f(-1.4426950408889634f * x)); }
__device__ __forceinline__ float tanhf_(float x) {
    float xc = fminf(fmaxf(x, -15.0f), 15.0f);
    float e = ex2f(2.8853900817779268f * xc);
    return (e - 1.0f) * rcpf(e + 1.0f);
}

// ---------------- prep: permute weights to [k][p], p = jh*4 + gate ----------------
__global__ void prep_f32(const float* __restrict__ Whh, const float* __restrict__ Wih,
                         const float* __restrict__ bih, const float* __restrict__ bhh) {
    int idx = blockIdx.x * blockDim.x + threadIdx.x;
    if (idx >= 512 * 128) return;
    int g0 = idx >> 7, k = idx & 127;
    int gt = g0 >> 7, jh = g0 & 127;
    int p = jh * 4 + gt;
    g_Wp2[k * 512 + p] = Whh[g0 * 128 + k];
    if (k == 0) { g_wihp[p] = Wih[g0]; g_bp[p] = bih[g0] + bhh[g0]; }
}

__global__ void xt_k(const float* __restrict__ x) {
    int idx = blockIdx.x * blockDim.x + threadIdx.x;
    if (idx >= TT * NN) return;
    int t = idx / NN, n = idx % NN;
    g_xT[idx] = x[n * TT + t];
}

// ---------------- LSTM: packed-f32x2 FFMA, duplicated-h smem, cp.async W stream ----------
// smem (floats): hs float2[128][ROWW] = 18688 | wcs float[2][4096] = 8192 | aux 1024
#define HS_F   0
#define WCS_F  18688
#define AUX_F  26880
#define SMF    27904
#define SM_BYTES (SMF * 4)

__global__ __launch_bounds__(256, 1) void lstm_f32() {
    extern __shared__ __align__(16) float sm[];
    uint32_t sa = smem_u32(sm);
    int tid = threadIdx.x;
    int ng = tid >> 5;          // warp id: node-group (9 nodes)
    int gg = tid & 31;          // lane: gate-group (16 packed gates = 4 hidden x 4 gates)
    int n0 = ng * 9;
    int nbase = blockIdx.x * NPC;

    // init: aux, zero hs
    for (int i = tid; i < 512; i += 256) {
        sm[AUX_F + i] = g_wihp[i];
        sm[AUX_F + 512 + i] = g_bp[i];
    }
    for (int i = tid; i < 18688; i += 256) sm[HS_F + i] = 0.0f;
    __syncthreads();

    float c[36];
#pragma unroll
    for (int i = 0; i < 36; i++) c[i] = 0.0f;

    // prefetch W chunk 0 into buf 0 (chunk = 8 k-rows x 512 = 4096 floats = 1024 float4)
#pragma unroll
    for (int q = 0; q < 4; q++) {
        uint32_t dst = sa + (uint32_t)((WCS_F + tid * 4 + q * 1024) * 4);
        const float* src = g_Wp2 + tid * 4 + q * 1024;
        asm volatile("cp.async.cg.shared.global [%0], [%1], 16;" :: "r"(dst), "l"(src));
    }
    asm volatile("cp.async.commit_group;" ::: "memory");

    for (int t = 0; t < TT; t++) {
        unsigned long long acc[9][8];
#pragma unroll
        for (int i = 0; i < 9; i++)
#pragma unroll
            for (int j = 0; j < 8; j++) acc[i][j] = 0ull;

        for (int kc = 0; kc < 16; kc++) {
            __syncthreads();   // prev chunk compute done everywhere (also orders epilogue writes)
            if (kc < 15) {
                int nk = kc + 1;
#pragma unroll
                for (int q = 0; q < 4; q++) {
                    uint32_t dst = sa + (uint32_t)((WCS_F + (nk & 1) * 4096 + tid * 4 + q * 1024) * 4);
                    const float* src = g_Wp2 + nk * 4096 + tid * 4 + q * 1024;
                    asm volatile("cp.async.cg.shared.global [%0], [%1], 16;" :: "r"(dst), "l"(src));
                }
                asm volatile("cp.async.commit_group;" ::: "memory");
                asm volatile("cp.async.wait_group 1;" ::: "memory");
            } else {
                asm volatile("cp.async.wait_group 0;" ::: "memory");
            }
            __syncthreads();   // chunk kc visible to all warps

            const float* wrow = sm + WCS_F + (kc & 1) * 4096;
#pragma unroll
            for (int k8 = 0; k8 < 8; k8++) {
                int k = kc * 8 + k8;
                // 9 duplicated-h pairs (broadcast LDS.64)
                unsigned long long h2[9];
#pragma unroll
                for (int i = 0; i < 9; i++)
                    h2[i] = *(const unsigned long long*)(sm + HS_F + (k * ROWW + n0 + i) * 2);
                // 16 W floats = 4 LDS.128 = 8 ready-packed pairs
                ulonglong2 wv0 = *(const ulonglong2*)(wrow + k8 * 512 + gg * 16);
                ulonglong2 wv1 = *(const ulonglong2*)(wrow + k8 * 512 + gg * 16 + 4);
                ulonglong2 wv2 = *(const ulonglong2*)(wrow + k8 * 512 + gg * 16 + 8);
                ulonglong2 wv3 = *(const ulonglong2*)(wrow + k8 * 512 + gg * 16 + 12);
#pragma unroll
                for (int i = 0; i < 9; i++) {
                    fma2(acc[i][0], h2[i], wv0.x);
                    fma2(acc[i][1], h2[i], wv0.y);
                    fma2(acc[i][2], h2[i], wv1.x);
                    fma2(acc[i][3], h2[i], wv1.y);
                    fma2(acc[i][4], h2[i], wv2.x);
                    fma2(acc[i][5], h2[i], wv2.y);
                    fma2(acc[i][6], h2[i], wv3.x);
                    fma2(acc[i][7], h2[i], wv3.y);
                }
            }
        }
        __syncthreads();   // all hs reads of this step done before epilogue overwrites

        // epilogue: fold x*Wih + b, cell update, write duplicated h
        unsigned long long wih2[8], bb2[8];
#pragma unroll
        for (int j = 0; j < 8; j++) {
            wih2[j] = *(const unsigned long long*)(sm + AUX_F + gg * 16 + j * 2);
            bb2[j]  = *(const unsigned long long*)(sm + AUX_F + 512 + gg * 16 + j * 2);
        }
#pragma unroll
        for (int i = 0; i < 9; i++) {
            int gn = nbase + n0 + i;
            float xv = (gn < NN) ? __ldg(&g_xT[t * NN + gn]) : 0.0f;
            unsigned long long x2 = pack2(xv);
#pragma unroll
            for (int j = 0; j < 8; j++) {
                fma2(acc[i][j], x2, wih2[j]);
                add2(acc[i][j], bb2[j]);
            }
#pragma unroll
            for (int lj = 0; lj < 4; lj++) {
                float2 pif = unpack2(acc[i][2 * lj]);       // (i-gate, f-gate)
                float2 pgo = unpack2(acc[i][2 * lj + 1]);   // (g-gate, o-gate)
                float cn = sigf(pif.y) * c[i * 4 + lj] + sigf(pif.x) * tanhf_(pgo.x);
                c[i * 4 + lj] = cn;
                float h = sigf(pgo.y) * tanhf_(cn);
                int jh = gg * 4 + lj;
                *(float2*)(sm + HS_F + (jh * ROWW + n0 + i) * 2) = make_float2(h, h);
                if (t == TT - 1 && gn < NN)
                    g_h1[gn * HH + jh] = fmaxf(h, 0.0f);
            }
        }
        // prefetch chunk 0 for next step (buf 0 idle since chunk 14)
        if (t < TT - 1) {
#pragma unroll
            for (int q = 0; q < 4; q++) {
                uint32_t dst = sa + (uint32_t)((WCS_F + tid * 4 + q * 1024) * 4);
                const float* src = g_Wp2 + tid * 4 + q * 1024;
                asm volatile("cp.async.cg.shared.global [%0], [%1], 16;" :: "r"(dst), "l"(src));
            }
            asm volatile("cp.async.commit_group;" ::: "memory");
        }
    }
}

// ---------------- GCN dense GEMM: Y[N,128] = X[N,128] @ W[128,128] ----------------
__global__ __launch_bounds__(256) void gemm_k(const float* __restrict__ X,
                                              const float* __restrict__ W,
                                              float* __restrict__ Y, int N) {
    __shared__ __align__(16) float Xs[32][128];
    __shared__ __align__(16) float Ws[64][128];
    int tid = threadIdx.x;
    int node = tid >> 3;
    int jq = tid & 7;
    int j0 = jq * 16;
    int nb = blockIdx.x * 32;

    for (int idx = tid; idx < 32 * 128; idx += 256) {
        int n = idx >> 7, k = idx & 127;
        Xs[n][k] = (nb + n < N) ? X[(nb + n) * 128 + k] : 0.f;
    }
    float4 a0 = make_float4(0.f, 0.f, 0.f, 0.f), a1 = a0, a2 = a0, a3 = a0;

    for (int half = 0; half < 2; half++) {
        __syncthreads();
        for (int idx = tid; idx < 64 * 128; idx += 256) {
            int k = idx >> 7, j = idx & 127;
            Ws[k][j] = W[(half * 64 + k) * 128 + j];
        }
        __syncthreads();
#pragma unroll 8
        for (int k8 = 0; k8 < 64; k8++) {
            float xv = Xs[node][half * 64 + k8];
            const float4* wr = (const float4*)&Ws[k8][j0];
            float4 w0 = wr[0], w1 = wr[1], w2 = wr[2], w3 = wr[3];
            a0.x += xv * w0.x; a0.y += xv * w0.y; a0.z += xv * w0.z; a0.w += xv * w0.w;
            a1.x += xv * w1.x; a1.y += xv * w1.y; a1.z += xv * w1.z; a1.w += xv * w1.w;
            a2.x += xv * w2.x; a2.y += xv * w2.y; a2.z += xv * w2.z; a2.w += xv * w2.w;
            a3.x += xv * w3.x; a3.y += xv * w3.y; a3.z += xv * w3.z; a3.w += xv * w3.w;
        }
    }
    if (nb + node < N) {
        float4* yo = (float4*)&Y[(nb + node) * 128 + j0];
        yo[0] = a0; yo[1] = a1; yo[2] = a2; yo[3] = a3;
    }
}

// ---------------- graph normalization + scatter ----------------
__global__ void deg_init(int N) {
    int i = blockIdx.x * blockDim.x + threadIdx.x;
    if (i < N) g_deg[i] = 1.0f;
}
__global__ void deg_scatter(const int* __restrict__ col, const float* __restrict__ ew, int E) {
    int e = blockIdx.x * blockDim.x + threadIdx.x;
    if (e < E) atomicAdd(&g_deg[col[e]], ew[e]);
}
__global__ void dinv_k(int N) {
    int i = blockIdx.x * blockDim.x + threadIdx.x;
    if (i < N) g_dinv[i] = rsqrtf(g_deg[i]);
}
__global__ void norm_k(const int* __restrict__ row, const int* __restrict__ col,
                       const float* __restrict__ ew, int E) {
    int e = blockIdx.x * blockDim.x + threadIdx.x;
    if (e < E) g_norm[e] = g_dinv[row[e]] * ew[e] * g_dinv[col[e]];
}
__global__ void self_init(const float* __restrict__ src, float* __restrict__ dst, int N) {
    int gid = blockIdx.x * blockDim.x + threadIdx.x;
    if (gid >= N * 32) return;
    int n = gid >> 5;
    float d = g_dinv[n];
    float s = d * d;
    float4 v = ((const float4*)src)[gid];
    v.x *= s; v.y *= s; v.z *= s; v.w *= s;
    ((float4*)dst)[gid] = v;
}
__global__ void scatter_k(const float* __restrict__ src, float* __restrict__ dst,
                          const int* __restrict__ row, const int* __restrict__ col, int E) {
    int gid = blockIdx.x * blockDim.x + threadIdx.x;
    int e = gid >> 5;
    if (e >= E) return;
    int lane = gid & 31;
    int r = row[e], cc = col[e];
    float nv = g_norm[e];
    float4 v = ((const float4*)(src + r * 128))[lane];
    float* d = dst + cc * 128 + lane * 4;
    atomicAdd(d + 0, nv * v.x);
    atomicAdd(d + 1, nv * v.y);
    atomicAdd(d + 2, nv * v.z);
    atomicAdd(d + 3, nv * v.w);
}
__global__ void bias_relu(float* __restrict__ h, const float* __restrict__ b, int N) {
    int gid = blockIdx.x * blockDim.x + threadIdx.x;
    if (gid < N * 128) h[gid] = fmaxf(h[gid] + b[gid & 127], 0.f);
}
__global__ void pool_k(const float* __restrict__ h, const float* __restrict__ b2,
                       float* __restrict__ out, int N) {
    int f = blockIdx.x;
    float s = 0.f;
    for (int n = threadIdx.x; n < N; n += blockDim.x) s += h[n * 128 + f];
    __shared__ float red[256];
    red[threadIdx.x] = s;
    __syncthreads();
    for (int o = 128; o > 0; o >>= 1) {
        if (threadIdx.x < o) red[threadIdx.x] += red[threadIdx.x + o];
        __syncthreads();
    }
    if (threadIdx.x == 0) out[f] = red[0] / (float)N + b2[f];
}

// ---------------- launch ----------------
extern "C" void kernel_launch(void* const* d_in, const int* in_sizes, int n_in,
                              void* d_out, int out_size) {
    const float* x   = (const float*)d_in[0];
    const int*   ei  = (const int*)d_in[1];
    const float* ew  = (const float*)d_in[2];
    const float* Wih = (const float*)d_in[3];
    const float* Whh = (const float*)d_in[4];
    const float* bih = (const float*)d_in[5];
    const float* bhh = (const float*)d_in[6];
    const float* W1  = (const float*)d_in[7];
    const float* b1  = (const float*)d_in[8];
    const float* W2  = (const float*)d_in[9];
    const float* b2  = (const float*)d_in[10];
    float* out = (float*)d_out;

    int N = in_sizes[0] / TT;
    int E = in_sizes[2];
    const int* row = ei;
    const int* col = ei + E;

    float *p_h1, *p_xw, *p_h2, *p_h3;
    cudaGetSymbolAddress((void**)&p_h1, g_h1);
    cudaGetSymbolAddress((void**)&p_xw, g_xw);
    cudaGetSymbolAddress((void**)&p_h2, g_h2);
    cudaGetSymbolAddress((void**)&p_h3, g_h3);

    cudaFuncSetAttribute(lstm_f32, cudaFuncAttributeMaxDynamicSharedMemorySize, SM_BYTES);

    int nb256 = (N + 255) / 256;
    int eb256 = (E + 255) / 256;

    prep_f32<<<(512 * 128 + 255) / 256, 256>>>(Whh, Wih, bih, bhh);
    xt_k<<<(TT * NN + 255) / 256, 256>>>(x);
    lstm_f32<<<NCTA, 256, SM_BYTES>>>();               // 139 CTAs -> g_h1 (relu'd)

    deg_init<<<nb256, 256>>>(N);
    deg_scatter<<<eb256, 256>>>(col, ew, E);
    dinv_k<<<nb256, 256>>>(N);
    norm_k<<<eb256, 256>>>(row, col, ew, E);

    // GCN layer 1
    gemm_k<<<(N + 31) / 32, 256>>>(p_h1, W1, p_xw, N);
    self_init<<<(N * 32 + 255) / 256, 256>>>(p_xw, p_h2, N);
    scatter_k<<<(E * 32 + 255) / 256, 256>>>(p_xw, p_h2, row, col, E);
    bias_relu<<<(N * 128 + 255) / 256, 256>>>(p_h2, b1, N);

    // GCN layer 2
    gemm_k<<<(N + 31) / 32, 256>>>(p_h2, W2, p_xw, N);
    self_init<<<(N * 32 + 255) / 256, 256>>>(p_xw, p_h3, N);
    scatter_k<<<(E * 32 + 255) / 256, 256>>>(p_xw, p_h3, row, col, E);

    pool_k<<<128, 256>>>(p_h3, b2, out, N);
}

// round 10
// speedup vs baseline: 1.8204x; 1.8204x over previous
#include <cuda_runtime.h>
#include <math.h>
#include <stdint.h>

#define NN 10000
#define TT 128
#define HH 128
#define EE 320000
#define MCTA 80          // nodes per CTA (125 * 80 = 10000 exactly)
#define NCTA 125
#define KTILES 17        // K = 136 = 128 (h) + x + 1 + 5 pad

// ---------------- device scratch ----------------
__device__ __align__(16) float g_h1[NN * HH];
__device__ __align__(16) float g_xw[NN * HH];
__device__ __align__(16) float g_h2[NN * HH];
__device__ __align__(16) float g_h3[NN * HH];
__device__ __align__(16) float g_deg[NN];
__device__ __align__(16) float g_dinv[NN];
__device__ __align__(16) float g_norm[EE];
__device__ __align__(16) float g_xT[TT * NN];       // transposed input (raw fp32)
// B fragment order (R5-proven indexing): [kt 17][nw 8][nt 8][lane 32][reg 2]
__device__ __align__(16) float g_Bhi[KTILES * 8 * 512];
__device__ __align__(16) float g_Blo[KTILES * 8 * 512];

// ---------------- helpers ----------------
__device__ __forceinline__ uint32_t smem_u32(const void* p) {
    uint32_t a;
    asm("{ .reg .u64 t; cvta.to.shared.u64 t, %1; cvt.u32.u64 %0, t; }" : "=r"(a) : "l"(p));
    return a;
}
__device__ __forceinline__ float ex2f(float x) { float r; asm("ex2.approx.f32 %0, %1;" : "=f"(r) : "f"(x)); return r; }
__device__ __forceinline__ float rcpf(float x) { float r; asm("rcp.approx.f32 %0, %1;" : "=f"(r) : "f"(x)); return r; }
__device__ __forceinline__ float sigf(float x) { return rcpf(1.0f + ex2f(-1.4426950408889634f * x)); }
__device__ __forceinline__ float tanhf_(float x) {
    float xc = fminf(fmaxf(x, -15.0f), 15.0f);
    float e = ex2f(2.8853900817779268f * xc);
    return (e - 1.0f) * rcpf(e + 1.0f);
}
__device__ __forceinline__ uint32_t to_tf32(float x) {
    uint32_t v; asm("cvt.rna.tf32.f32 %0, %1;" : "=r"(v) : "f"(x)); return v;
}
__device__ __forceinline__ void mma_tf32(float& d0, float& d1, float& d2, float& d3,
                                         uint32_t a0, uint32_t a1, uint32_t a2, uint32_t a3,
                                         uint32_t b0, uint32_t b1) {
    asm volatile("mma.sync.aligned.m16n8k8.row.col.f32.tf32.tf32.f32 "
                 "{%0,%1,%2,%3}, {%4,%5,%6,%7}, {%8,%9}, {%0,%1,%2,%3};"
                 : "+f"(d0), "+f"(d1), "+f"(d2), "+f"(d3)
                 : "r"(a0), "r"(a1), "r"(a2), "r"(a3), "r"(b0), "r"(b1));
}
// ORDERED shared loads: volatile + memory clobber so they can never be
// hoisted/CSE'd across cp.async waits or epilogue stores.
#define LDSV4(r0, r1, r2, r3, addr) \
    asm volatile("ld.shared.v4.b32 {%0,%1,%2,%3}, [%4];" \
        : "=r"(r0), "=r"(r1), "=r"(r2), "=r"(r3) : "r"(addr) : "memory")
#define LDSV2(r0, r1, addr) \
    asm volatile("ld.shared.v2.b32 {%0,%1}, [%2];" \
        : "=r"(r0), "=r"(r1) : "r"(addr) : "memory")

// ---------------- prep: B fragment-order, hi + lo tf32 split ----------------
// D column d = gt*128 + jh. Warp nw owns jh in [nw*16, nw*16+16).
// nt = gt*2 + (jl/8), nlo = jl%8. B frag (m16n8k8 col-major): (k,n) -> lane=n*4+(k%4), reg=k/4.
// B rows: k<128: Whh[d][k]; k=128: Wih[d]; k=129: bih[d]+bhh[d]; else 0.
__global__ void prep_tc(const float* __restrict__ Whh, const float* __restrict__ Wih,
                        const float* __restrict__ bih, const float* __restrict__ bhh) {
    int idx = blockIdx.x * blockDim.x + threadIdx.x;
    if (idx >= 512 * 136) return;
    int d = idx / 136, k = idx % 136;
    float v;
    if (k < 128)       v = Whh[d * 128 + k];
    else if (k == 128) v = Wih[d];
    else if (k == 129) v = bih[d] + bhh[d];
    else               v = 0.0f;
    uint32_t hi = to_tf32(v);
    float lo = v - __uint_as_float(hi);
    int gt = d >> 7, jh = d & 127;
    int nw = jh >> 4, jl = jh & 15;
    int nt = gt * 2 + (jl >> 3), nlo = jl & 7;
    int kt = k >> 3, kl = k & 7;
    int lane = nlo * 4 + (kl & 3), reg = kl >> 2;
    int fi = ((((kt * 8) + nw) * 8 + nt) * 32 + lane) * 2 + reg;
    g_Bhi[fi] = __uint_as_float(hi);
    g_Blo[fi] = __uint_as_float(to_tf32(lo));
}

__global__ void xt_k(const float* __restrict__ x) {
    int idx = blockIdx.x * blockDim.x + threadIdx.x;
    if (idx >= TT * NN) return;
    int t = idx / NN, n = idx % NN;
    g_xT[idx] = x[n * TT + t];
}

// ---------------- LSTM: 3-term tf32 mma.sync, ordered loads ----------------
// smem floats: AH 10880 | AL 10880 | BH 2x4096 | BL 2x4096 | CC 256*41
#define AH_F   0
#define AL_F   10880
#define BH_F   21760
#define BL_F   29952
#define CC_F   38144
#define SMF    (38144 + 256 * 41)
#define SM_BYTES (SMF * 4)

__global__ __launch_bounds__(256, 1) void lstm_tc() {
    extern __shared__ __align__(16) float sm[];
    uint32_t sa = smem_u32(sm);
    int tid = threadIdx.x;
    int nw = tid >> 5;          // warp id = N-slice 0..7
    int lane = tid & 31;
    int nbase = blockIdx.x * MCTA;

    // zero all smem regions (A planes, BOTH B buffers, c)
    for (int i = tid; i < SMF; i += 256) sm[i] = 0.0f;
    __syncthreads();
    // ones col (k=129) into AH; x0 hi/lo into AH/AL col k=128
    if (tid < MCTA) {
        int n = tid, mt = n >> 4, r = n & 15;
        int lane1 = ((r & 7) << 2) + 1, reg1 = r >> 3;        // k=129 -> kl=1
        int lane0 = ((r & 7) << 2) + 0, reg0 = r >> 3;        // k=128 -> kl=0
        sm[AH_F + ((mt * KTILES + 16) * 32 + lane1) * 4 + reg1] = 1.0f;
        float xv = g_xT[0 * NN + nbase + n];
        uint32_t xhi = to_tf32(xv);
        float xlo = xv - __uint_as_float(xhi);
        int ai = ((mt * KTILES + 16) * 32 + lane0) * 4 + reg0;
        sm[AH_F + ai] = __uint_as_float(xhi);
        sm[AL_F + ai] = __uint_as_float(to_tf32(xlo));
    }
    __syncthreads();

    for (int t = 0; t < TT; t++) {
        float acc[8][5][4];
#pragma unroll
        for (int nt = 0; nt < 8; nt++)
#pragma unroll
            for (int mt = 0; mt < 5; mt++)
#pragma unroll
                for (int q = 0; q < 4; q++) acc[nt][mt][q] = 0.0f;

        // prefetch k-tile 0 (warp's hi + lo slices, 2KB each)
#pragma unroll
        for (int rr = 0; rr < 4; rr++) {
            uint32_t dh = sa + (uint32_t)((BH_F + nw * 512 + lane * 4 + rr * 128) * 4);
            const float* sh = g_Bhi + ((0 * 8 + nw) * 512 + lane * 4 + rr * 128);
            asm volatile("cp.async.cg.shared.global [%0], [%1], 16;" :: "r"(dh), "l"(sh));
            uint32_t dl = sa + (uint32_t)((BL_F + nw * 512 + lane * 4 + rr * 128) * 4);
            const float* sl = g_Blo + ((0 * 8 + nw) * 512 + lane * 4 + rr * 128);
            asm volatile("cp.async.cg.shared.global [%0], [%1], 16;" :: "r"(dl), "l"(sl));
        }
        asm volatile("cp.async.commit_group;" ::: "memory");

        for (int kt = 0; kt < KTILES; kt++) {
            if (kt < KTILES - 1) {
                int nk = kt + 1;
                int off = (nk & 1) * 4096;
#pragma unroll
                for (int rr = 0; rr < 4; rr++) {
                    uint32_t dh = sa + (uint32_t)((BH_F + off + nw * 512 + lane * 4 + rr * 128) * 4);
                    const float* sh = g_Bhi + ((nk * 8 + nw) * 512 + lane * 4 + rr * 128);
                    asm volatile("cp.async.cg.shared.global [%0], [%1], 16;" :: "r"(dh), "l"(sh));
                    uint32_t dl = sa + (uint32_t)((BL_F + off + nw * 512 + lane * 4 + rr * 128) * 4);
                    const float* sl = g_Blo + ((nk * 8 + nw) * 512 + lane * 4 + rr * 128);
                    asm volatile("cp.async.cg.shared.global [%0], [%1], 16;" :: "r"(dl), "l"(sl));
                }
                asm volatile("cp.async.commit_group;" ::: "memory");
                asm volatile("cp.async.wait_group 1;" ::: "memory");
            } else {
                asm volatile("cp.async.wait_group 0;" ::: "memory");
            }
            __syncwarp();

            // B fragments (hi + lo) — ordered loads, cached for this k-tile
            uint32_t bh[8][2], bl[8][2];
            uint32_t bhib = sa + (uint32_t)((BH_F + (kt & 1) * 4096 + nw * 512) * 4);
            uint32_t blob = sa + (uint32_t)((BL_F + (kt & 1) * 4096 + nw * 512) * 4);
#pragma unroll
            for (int nt = 0; nt < 8; nt++) {
                LDSV2(bh[nt][0], bh[nt][1], bhib + (uint32_t)((nt * 32 + lane) * 8));
                LDSV2(bl[nt][0], bl[nt][1], blob + (uint32_t)((nt * 32 + lane) * 8));
            }
            // A frags streamed; 3 MMAs per (mt, nt)
#pragma unroll
            for (int mt = 0; mt < 5; mt++) {
                uint32_t ah0, ah1, ah2, ah3, al0, al1, al2, al3;
                uint32_t aaddr = sa + (uint32_t)((((mt * KTILES + kt) * 32 + lane) * 4) * 4);
                LDSV4(ah0, ah1, ah2, ah3, aaddr);
                LDSV4(al0, al1, al2, al3, aaddr + (uint32_t)(AL_F * 4));
#pragma unroll
                for (int nt = 0; nt < 8; nt++) {
                    mma_tf32(acc[nt][mt][0], acc[nt][mt][1], acc[nt][mt][2], acc[nt][mt][3],
                             ah0, ah1, ah2, ah3, bh[nt][0], bh[nt][1]);
                    mma_tf32(acc[nt][mt][0], acc[nt][mt][1], acc[nt][mt][2], acc[nt][mt][3],
                             ah0, ah1, ah2, ah3, bl[nt][0], bl[nt][1]);
                    mma_tf32(acc[nt][mt][0], acc[nt][mt][1], acc[nt][mt][2], acc[nt][mt][3],
                             al0, al1, al2, al3, bh[nt][0], bh[nt][1]);
                }
            }
        }
        __syncthreads();   // all A reads done before epilogue overwrites A

        // epilogue: cell update; c lives in smem (stride 41, conflict-free)
#pragma unroll
        for (int mt = 0; mt < 5; mt++) {
#pragma unroll
            for (int rh = 0; rh < 2; rh++) {
                int r = (lane >> 2) + rh * 8;
                int n = mt * 16 + r;
#pragma unroll
                for (int jt = 0; jt < 2; jt++) {
#pragma unroll
                    for (int nlo = 0; nlo < 2; nlo++) {
                        int ci = ((mt * 2 + rh) * 2 + jt) * 2 + nlo;
                        int q = rh * 2 + nlo;
                        float pi = acc[0 + jt][mt][q];
                        float pf = acc[2 + jt][mt][q];
                        float pg = acc[4 + jt][mt][q];
                        float po = acc[6 + jt][mt][q];
                        float cold = sm[CC_F + tid * 41 + ci];
                        float cn = sigf(pf) * cold + sigf(pi) * tanhf_(pg);
                        sm[CC_F + tid * 41 + ci] = cn;
                        float h = sigf(po) * tanhf_(cn);
                        int jh = nw * 16 + jt * 8 + ((lane & 3) << 1) + nlo;
                        int kt2 = jh >> 3, kl = jh & 7;
                        int lane2 = ((r & 7) << 2) + (kl & 3);
                        int reg2 = (r >> 3) + ((kl >> 2) << 1);
                        int ai = ((mt * KTILES + kt2) * 32 + lane2) * 4 + reg2;
                        uint32_t hhi = to_tf32(h);
                        float hlo = h - __uint_as_float(hhi);
                        sm[AH_F + ai] = __uint_as_float(hhi);
                        sm[AL_F + ai] = __uint_as_float(to_tf32(hlo));
                        if (t == TT - 1 && nbase + n < NN)
                            g_h1[(nbase + n) * HH + jh] = fmaxf(h, 0.0f);
                    }
                }
            }
        }
        // x hi/lo for next step
        if (t < TT - 1 && tid < MCTA) {
            int n = tid, mt = n >> 4, r = n & 15;
            int lane0 = ((r & 7) << 2), reg0 = r >> 3;
            float xv = g_xT[(t + 1) * NN + nbase + n];
            uint32_t xhi = to_tf32(xv);
            float xlo = xv - __uint_as_float(xhi);
            int ai = ((mt * KTILES + 16) * 32 + lane0) * 4 + reg0;
            sm[AH_F + ai] = __uint_as_float(xhi);
            sm[AL_F + ai] = __uint_as_float(to_tf32(xlo));
        }
        __syncthreads();
    }
}

// ---------------- GCN dense GEMM: Y[N,128] = X[N,128] @ W[128,128] ----------------
__global__ __launch_bounds__(256) void gemm_k(const float* __restrict__ X,
                                              const float* __restrict__ W,
                                              float* __restrict__ Y, int N) {
    __shared__ __align__(16) float Xs[32][128];
    __shared__ __align__(16) float Ws[64][128];
    int tid = threadIdx.x;
    int node = tid >> 3;
    int jq = tid & 7;
    int j0 = jq * 16;
    int nb = blockIdx.x * 32;

    for (int idx = tid; idx < 32 * 128; idx += 256) {
        int n = idx >> 7, k = idx & 127;
        Xs[n][k] = (nb + n < N) ? X[(nb + n) * 128 + k] : 0.f;
    }
    float4 a0 = make_float4(0.f, 0.f, 0.f, 0.f), a1 = a0, a2 = a0, a3 = a0;

    for (int half = 0; half < 2; half++) {
        __syncthreads();
        for (int idx = tid; idx < 64 * 128; idx += 256) {
            int k = idx >> 7, j = idx & 127;
            Ws[k][j] = W[(half * 64 + k) * 128 + j];
        }
        __syncthreads();
#pragma unroll 8
        for (int k8 = 0; k8 < 64; k8++) {
            float xv = Xs[node][half * 64 + k8];
            const float4* wr = (const float4*)&Ws[k8][j0];
            float4 w0 = wr[0], w1 = wr[1], w2 = wr[2], w3 = wr[3];
            a0.x += xv * w0.x; a0.y += xv * w0.y; a0.z += xv * w0.z; a0.w += xv * w0.w;
            a1.x += xv * w1.x; a1.y += xv * w1.y; a1.z += xv * w1.z; a1.w += xv * w1.w;
            a2.x += xv * w2.x; a2.y += xv * w2.y; a2.z += xv * w2.z; a2.w += xv * w2.w;
            a3.x += xv * w3.x; a3.y += xv * w3.y; a3.z += xv * w3.z; a3.w += xv * w3.w;
        }
    }
    if (nb + node < N) {
        float4* yo = (float4*)&Y[(nb + node) * 128 + j0];
        yo[0] = a0; yo[1] = a1; yo[2] = a2; yo[3] = a3;
    }
}

// ---------------- graph normalization + scatter ----------------
__global__ void deg_init(int N) {
    int i = blockIdx.x * blockDim.x + threadIdx.x;
    if (i < N) g_deg[i] = 1.0f;
}
__global__ void deg_scatter(const int* __restrict__ col, const float* __restrict__ ew, int E) {
    int e = blockIdx.x * blockDim.x + threadIdx.x;
    if (e < E) atomicAdd(&g_deg[col[e]], ew[e]);
}
__global__ void dinv_k(int N) {
    int i = blockIdx.x * blockDim.x + threadIdx.x;
    if (i < N) g_dinv[i] = rsqrtf(g_deg[i]);
}
__global__ void norm_k(const int* __restrict__ row, const int* __restrict__ col,
                       const float* __restrict__ ew, int E) {
    int e = blockIdx.x * blockDim.x + threadIdx.x;
    if (e < E) g_norm[e] = g_dinv[row[e]] * ew[e] * g_dinv[col[e]];
}
__global__ void self_init(const float* __restrict__ src, float* __restrict__ dst, int N) {
    int gid = blockIdx.x * blockDim.x + threadIdx.x;
    if (gid >= N * 32) return;
    int n = gid >> 5;
    float d = g_dinv[n];
    float s = d * d;
    float4 v = ((const float4*)src)[gid];
    v.x *= s; v.y *= s; v.z *= s; v.w *= s;
    ((float4*)dst)[gid] = v;
}
__global__ void scatter_k(const float* __restrict__ src, float* __restrict__ dst,
                          const int* __restrict__ row, const int* __restrict__ col, int E) {
    int gid = blockIdx.x * blockDim.x + threadIdx.x;
    int e = gid >> 5;
    if (e >= E) return;
    int lane = gid & 31;
    int r = row[e], cc = col[e];
    float nv = g_norm[e];
    float4 v = ((const float4*)(src + r * 128))[lane];
    float* d = dst + cc * 128 + lane * 4;
    atomicAdd(d + 0, nv * v.x);
    atomicAdd(d + 1, nv * v.y);
    atomicAdd(d + 2, nv * v.z);
    atomicAdd(d + 3, nv * v.w);
}
__global__ void bias_relu(float* __restrict__ h, const float* __restrict__ b, int N) {
    int gid = blockIdx.x * blockDim.x + threadIdx.x;
    if (gid < N * 128) h[gid] = fmaxf(h[gid] + b[gid & 127], 0.f);
}
__global__ void pool_k(const float* __restrict__ h, const float* __restrict__ b2,
                       float* __restrict__ out, int N) {
    int f = blockIdx.x;
    float s = 0.f;
    for (int n = threadIdx.x; n < N; n += blockDim.x) s += h[n * 128 + f];
    __shared__ float red[256];
    red[threadIdx.x] = s;
    __syncthreads();
    for (int o = 128; o > 0; o >>= 1) {
        if (threadIdx.x < o) red[threadIdx.x] += red[threadIdx.x + o];
        __syncthreads();
    }
    if (threadIdx.x == 0) out[f] = red[0] / (float)N + b2[f];
}

// ---------------- launch ----------------
extern "C" void kernel_launch(void* const* d_in, const int* in_sizes, int n_in,
                              void* d_out, int out_size) {
    const float* x   = (const float*)d_in[0];
    const int*   ei  = (const int*)d_in[1];
    const float* ew  = (const float*)d_in[2];
    const float* Wih = (const float*)d_in[3];
    const float* Whh = (const float*)d_in[4];
    const float* bih = (const float*)d_in[5];
    const float* bhh = (const float*)d_in[6];
    const float* W1  = (const float*)d_in[7];
    const float* b1  = (const float*)d_in[8];
    const float* W2  = (const float*)d_in[9];
    const float* b2  = (const float*)d_in[10];
    float* out = (float*)d_out;

    int N = in_sizes[0] / TT;
    int E = in_sizes[2];
    const int* row = ei;
    const int* col = ei + E;

    float *p_h1, *p_xw, *p_h2, *p_h3;
    cudaGetSymbolAddress((void**)&p_h1, g_h1);
    cudaGetSymbolAddress((void**)&p_xw, g_xw);
    cudaGetSymbolAddress((void**)&p_h2, g_h2);
    cudaGetSymbolAddress((void**)&p_h3, g_h3);

    cudaFuncSetAttribute(lstm_tc, cudaFuncAttributeMaxDynamicSharedMemorySize, SM_BYTES);

    int nb256 = (N + 255) / 256;
    int eb256 = (E + 255) / 256;

    prep_tc<<<(512 * 136 + 255) / 256, 256>>>(Whh, Wih, bih, bhh);
    xt_k<<<(TT * NN + 255) / 256, 256>>>(x);
    lstm_tc<<<NCTA, 256, SM_BYTES>>>();                // 125 CTAs -> g_h1 (relu'd)

    deg_init<<<nb256, 256>>>(N);
    deg_scatter<<<eb256, 256>>>(col, ew, E);
    dinv_k<<<nb256, 256>>>(N);
    norm_k<<<eb256, 256>>>(row, col, ew, E);

    // GCN layer 1
    gemm_k<<<(N + 31) / 32, 256>>>(p_h1, W1, p_xw, N);
    self_init<<<(N * 32 + 255) / 256, 256>>>(p_xw, p_h2, N);
    scatter_k<<<(E * 32 + 255) / 256, 256>>>(p_xw, p_h2, row, col, E);
    bias_relu<<<(N * 128 + 255) / 256, 256>>>(p_h2, b1, N);

    // GCN layer 2
    gemm_k<<<(N + 31) / 32, 256>>>(p_h2, W2, p_xw, N);
    self_init<<<(N * 32 + 255) / 256, 256>>>(p_xw, p_h3, N);
    scatter_k<<<(E * 32 + 255) / 256, 256>>>(p_xw, p_h3, row, col, E);

    pool_k<<<128, 256>>>(p_h3, b2, out, N);
}

// round 12
// speedup vs baseline: 2.4291x; 1.3343x over previous
#include <cuda_runtime.h>
#include <math.h>
#include <stdint.h>

#define NN 10000
#define TT 128
#define HH 128
#define EE 320000
#define MCTA 80          // nodes per CTA (125 * 80 = 10000 exactly)
#define NCTA 125
#define KTILES 17        // K = 136 = 128 (h) + x + 1 + 5 pad

// ---------------- device scratch ----------------
__device__ __align__(16) float g_h1[NN * HH];
__device__ __align__(16) float g_xw[NN * HH];
__device__ __align__(16) float g_h2[NN * HH];
__device__ __align__(16) float g_h3[NN * HH];
__device__ __align__(16) float g_deg[NN];
__device__ __align__(16) float g_dinv[NN];
__device__ __align__(16) float g_norm[EE];
__device__ __align__(16) float g_xT[TT * NN];       // transposed input (raw fp32)
// B fragment order (proven indexing): [kt 17][nw 8][nt 8][lane 32][reg 2]
__device__ __align__(16) float g_Bhi[KTILES * 8 * 512];
__device__ __align__(16) float g_Blo[KTILES * 8 * 512];

// ---------------- helpers ----------------
__device__ __forceinline__ uint32_t smem_u32(const void* p) {
    uint32_t a;
    asm("{ .reg .u64 t; cvta.to.shared.u64 t, %1; cvt.u32.u64 %0, t; }" : "=r"(a) : "l"(p));
    return a;
}
__device__ __forceinline__ float ex2f(float x) { float r; asm("ex2.approx.f32 %0, %1;" : "=f"(r) : "f"(x)); return r; }
__device__ __forceinline__ float rcpf(float x) { float r; asm("rcp.approx.f32 %0, %1;" : "=f"(r) : "f"(x)); return r; }
__device__ __forceinline__ float sigf(float x) { return rcpf(1.0f + ex2f(-1.4426950408889634f * x)); }
__device__ __forceinline__ float tanhf_(float x) {
    float xc = fminf(fmaxf(x, -15.0f), 15.0f);
    float e = ex2f(2.8853900817779268f * xc);
    return (e - 1.0f) * rcpf(e + 1.0f);
}
__device__ __forceinline__ uint32_t to_tf32(float x) {
    uint32_t v; asm("cvt.rna.tf32.f32 %0, %1;" : "=r"(v) : "f"(x)); return v;
}
__device__ __forceinline__ void mma_tf32(float& d0, float& d1, float& d2, float& d3,
                                         uint32_t a0, uint32_t a1, uint32_t a2, uint32_t a3,
                                         uint32_t b0, uint32_t b1) {
    asm volatile("mma.sync.aligned.m16n8k8.row.col.f32.tf32.tf32.f32 "
                 "{%0,%1,%2,%3}, {%4,%5,%6,%7}, {%8,%9}, {%0,%1,%2,%3};"
                 : "+f"(d0), "+f"(d1), "+f"(d2), "+f"(d3)
                 : "r"(a0), "r"(a1), "r"(a2), "r"(a3), "r"(b0), "r"(b1));
}
// ORDERED shared loads: volatile + memory clobber — never hoisted across
// cp.async waits or epilogue stores. (This fixed the R6/R7 corruption.)
#define LDSV4(r0, r1, r2, r3, addr) \
    asm volatile("ld.shared.v4.b32 {%0,%1,%2,%3}, [%4];" \
        : "=r"(r0), "=r"(r1), "=r"(r2), "=r"(r3) : "r"(addr) : "memory")
#define LDSV2(r0, r1, addr) \
    asm volatile("ld.shared.v2.b32 {%0,%1}, [%2];" \
        : "=r"(r0), "=r"(r1) : "r"(addr) : "memory")

// ---------------- prep: B fragment-order, hi + lo tf32 split ----------------
// D column d = gt*128 + jh. Warp nw owns jh in [nw*16, nw*16+16).
// nt = gt*2 + (jl/8), nlo = jl%8. B frag (m16n8k8 col-major): (k,n) -> lane=n*4+(k%4), reg=k/4.
// B rows: k<128: Whh[d][k]; k=128: Wih[d]; k=129: bih[d]+bhh[d]; else 0.
__global__ void prep_tc(const float* __restrict__ Whh, const float* __restrict__ Wih,
                        const float* __restrict__ bih, const float* __restrict__ bhh) {
    int idx = blockIdx.x * blockDim.x + threadIdx.x;
    if (idx >= 512 * 136) return;
    int d = idx / 136, k = idx % 136;
    float v;
    if (k < 128)       v = Whh[d * 128 + k];
    else if (k == 128) v = Wih[d];
    else if (k == 129) v = bih[d] + bhh[d];
    else               v = 0.0f;
    uint32_t hi = to_tf32(v);
    float lo = v - __uint_as_float(hi);
    int gt = d >> 7, jh = d & 127;
    int nw = jh >> 4, jl = jh & 15;
    int nt = gt * 2 + (jl >> 3), nlo = jl & 7;
    int kt = k >> 3, kl = k & 7;
    int lane = nlo * 4 + (kl & 3), reg = kl >> 2;
    int fi = ((((kt * 8) + nw) * 8 + nt) * 32 + lane) * 2 + reg;
    g_Bhi[fi] = __uint_as_float(hi);
    g_Blo[fi] = __uint_as_float(to_tf32(lo));
}

__global__ void xt_k(const float* __restrict__ x) {
    int idx = blockIdx.x * blockDim.x + threadIdx.x;
    if (idx >= TT * NN) return;
    int t = idx / NN, n = idx % NN;
    g_xT[idx] = x[n * TT + t];
}

// ---------------- LSTM: 2-term tf32 mma.sync (AH·BH + AH·BL), ordered loads ----------------
// smem floats: AH 10880 | BH 2x4096 | BL 2x4096 | CC 256*41
#define AH_F   0
#define BH_F   10880
#define BL_F   19072
#define CC_F   27264
#define SMF    (27264 + 256 * 41)
#define SM_BYTES (SMF * 4)

__global__ __launch_bounds__(256, 1) void lstm_tc() {
    extern __shared__ __align__(16) float sm[];
    uint32_t sa = smem_u32(sm);
    int tid = threadIdx.x;
    int nw = tid >> 5;          // warp id = N-slice 0..7
    int lane = tid & 31;
    int nbase = blockIdx.x * MCTA;

    // zero all smem regions (A plane, BOTH B buffers, c)
    for (int i = tid; i < SMF; i += 256) sm[i] = 0.0f;
    __syncthreads();
    // ones col (k=129) and x0 (k=128) into AH
    if (tid < MCTA) {
        int n = tid, mt = n >> 4, r = n & 15;
        int lane1 = ((r & 7) << 2) + 1, reg1 = r >> 3;        // k=129 -> kl=1
        int lane0 = ((r & 7) << 2) + 0, reg0 = r >> 3;        // k=128 -> kl=0
        sm[AH_F + ((mt * KTILES + 16) * 32 + lane1) * 4 + reg1] = 1.0f;
        float xv = g_xT[0 * NN + nbase + n];
        sm[AH_F + ((mt * KTILES + 16) * 32 + lane0) * 4 + reg0] =
            __uint_as_float(to_tf32(xv));
    }
    __syncthreads();

    for (int t = 0; t < TT; t++) {
        float acc[8][5][4];
#pragma unroll
        for (int nt = 0; nt < 8; nt++)
#pragma unroll
            for (int mt = 0; mt < 5; mt++)
#pragma unroll
                for (int q = 0; q < 4; q++) acc[nt][mt][q] = 0.0f;

        // prefetch k-tile 0 (warp's hi + lo slices, 2KB each)
#pragma unroll
        for (int rr = 0; rr < 4; rr++) {
            uint32_t dh = sa + (uint32_t)((BH_F + nw * 512 + lane * 4 + rr * 128) * 4);
            const float* sh = g_Bhi + ((0 * 8 + nw) * 512 + lane * 4 + rr * 128);
            asm volatile("cp.async.cg.shared.global [%0], [%1], 16;" :: "r"(dh), "l"(sh));
            uint32_t dl = sa + (uint32_t)((BL_F + nw * 512 + lane * 4 + rr * 128) * 4);
            const float* sl = g_Blo + ((0 * 8 + nw) * 512 + lane * 4 + rr * 128);
            asm volatile("cp.async.cg.shared.global [%0], [%1], 16;" :: "r"(dl), "l"(sl));
        }
        asm volatile("cp.async.commit_group;" ::: "memory");

        for (int kt = 0; kt < KTILES; kt++) {
            if (kt < KTILES - 1) {
                int nk = kt + 1;
                int off = (nk & 1) * 4096;
#pragma unroll
                for (int rr = 0; rr < 4; rr++) {
                    uint32_t dh = sa + (uint32_t)((BH_F + off + nw * 512 + lane * 4 + rr * 128) * 4);
                    const float* sh = g_Bhi + ((nk * 8 + nw) * 512 + lane * 4 + rr * 128);
                    asm volatile("cp.async.cg.shared.global [%0], [%1], 16;" :: "r"(dh), "l"(sh));
                    uint32_t dl = sa + (uint32_t)((BL_F + off + nw * 512 + lane * 4 + rr * 128) * 4);
                    const float* sl = g_Blo + ((nk * 8 + nw) * 512 + lane * 4 + rr * 128);
                    asm volatile("cp.async.cg.shared.global [%0], [%1], 16;" :: "r"(dl), "l"(sl));
                }
                asm volatile("cp.async.commit_group;" ::: "memory");
                asm volatile("cp.async.wait_group 1;" ::: "memory");
            } else {
                asm volatile("cp.async.wait_group 0;" ::: "memory");
            }
            __syncwarp();

            // B fragments (hi + lo) — ordered loads, cached for this k-tile
            uint32_t bh[8][2], bl[8][2];
            uint32_t bhib = sa + (uint32_t)((BH_F + (kt & 1) * 4096 + nw * 512) * 4);
            uint32_t blob = sa + (uint32_t)((BL_F + (kt & 1) * 4096 + nw * 512) * 4);
#pragma unroll
            for (int nt = 0; nt < 8; nt++) {
                LDSV2(bh[nt][0], bh[nt][1], bhib + (uint32_t)((nt * 32 + lane) * 8));
                LDSV2(bl[nt][0], bl[nt][1], blob + (uint32_t)((nt * 32 + lane) * 8));
            }
            // A frags streamed; 2 MMAs per (mt, nt)
#pragma unroll
            for (int mt = 0; mt < 5; mt++) {
                uint32_t ah0, ah1, ah2, ah3;
                uint32_t aaddr = sa + (uint32_t)((((mt * KTILES + kt) * 32 + lane) * 4) * 4);
                LDSV4(ah0, ah1, ah2, ah3, aaddr);
#pragma unroll
                for (int nt = 0; nt < 8; nt++) {
                    mma_tf32(acc[nt][mt][0], acc[nt][mt][1], acc[nt][mt][2], acc[nt][mt][3],
                             ah0, ah1, ah2, ah3, bh[nt][0], bh[nt][1]);
                    mma_tf32(acc[nt][mt][0], acc[nt][mt][1], acc[nt][mt][2], acc[nt][mt][3],
                             ah0, ah1, ah2, ah3, bl[nt][0], bl[nt][1]);
                }
            }
        }
        __syncthreads();   // all A reads done before epilogue overwrites A

        // epilogue: cell update; c lives in smem (stride 41, conflict-free)
#pragma unroll
        for (int mt = 0; mt < 5; mt++) {
#pragma unroll
            for (int rh = 0; rh < 2; rh++) {
                int r = (lane >> 2) + rh * 8;
                int n = mt * 16 + r;
#pragma unroll
                for (int jt = 0; jt < 2; jt++) {
#pragma unroll
                    for (int nlo = 0; nlo < 2; nlo++) {
                        int ci = ((mt * 2 + rh) * 2 + jt) * 2 + nlo;
                        int q = rh * 2 + nlo;
                        float pi = acc[0 + jt][mt][q];
                        float pf = acc[2 + jt][mt][q];
                        float pg = acc[4 + jt][mt][q];
                        float po = acc[6 + jt][mt][q];
                        float cold = sm[CC_F + tid * 41 + ci];
                        float cn = sigf(pf) * cold + sigf(pi) * tanhf_(pg);
                        sm[CC_F + tid * 41 + ci] = cn;
                        float h = sigf(po) * tanhf_(cn);
                        int jh = nw * 16 + jt * 8 + ((lane & 3) << 1) + nlo;
                        int kt2 = jh >> 3, kl = jh & 7;
                        int lane2 = ((r & 7) << 2) + (kl & 3);
                        int reg2 = (r >> 3) + ((kl >> 2) << 1);
                        sm[AH_F + ((mt * KTILES + kt2) * 32 + lane2) * 4 + reg2] =
                            __uint_as_float(to_tf32(h));
                        if (t == TT - 1 && nbase + n < NN)
                            g_h1[(nbase + n) * HH + jh] = fmaxf(h, 0.0f);
                    }
                }
            }
        }
        // x for next step
        if (t < TT - 1 && tid < MCTA) {
            int n = tid, mt = n >> 4, r = n & 15;
            int lane0 = ((r & 7) << 2), reg0 = r >> 3;
            float xv = g_xT[(t + 1) * NN + nbase + n];
            sm[AH_F + ((mt * KTILES + 16) * 32 + lane0) * 4 + reg0] =
                __uint_as_float(to_tf32(xv));
        }
        __syncthreads();
    }
}

// ---------------- GCN dense GEMM: Y[N,128] = X[N,128] @ W[128,128] ----------------
__global__ __launch_bounds__(256) void gemm_k(const float* __restrict__ X,
                                              const float* __restrict__ W,
                                              float* __restrict__ Y, int N) {
    __shared__ __align__(16) float Xs[32][128];
    __shared__ __align__(16) float Ws[64][128];
    int tid = threadIdx.x;
    int node = tid >> 3;
    int jq = tid & 7;
    int j0 = jq * 16;
    int nb = blockIdx.x * 32;

    for (int idx = tid; idx < 32 * 128; idx += 256) {
        int n = idx >> 7, k = idx & 127;
        Xs[n][k] = (nb + n < N) ? X[(nb + n) * 128 + k] : 0.f;
    }
    float4 a0 = make_float4(0.f, 0.f, 0.f, 0.f), a1 = a0, a2 = a0, a3 = a0;

    for (int half = 0; half < 2; half++) {
        __syncthreads();
        for (int idx = tid; idx < 64 * 128; idx += 256) {
            int k = idx >> 7, j = idx & 127;
            Ws[k][j] = W[(half * 64 + k) * 128 + j];
        }
        __syncthreads();
#pragma unroll 8
        for (int k8 = 0; k8 < 64; k8++) {
            float xv = Xs[node][half * 64 + k8];
            const float4* wr = (const float4*)&Ws[k8][j0];
            float4 w0 = wr[0], w1 = wr[1], w2 = wr[2], w3 = wr[3];
            a0.x += xv * w0.x; a0.y += xv * w0.y; a0.z += xv * w0.z; a0.w += xv * w0.w;
            a1.x += xv * w1.x; a1.y += xv * w1.y; a1.z += xv * w1.z; a1.w += xv * w1.w;
            a2.x += xv * w2.x; a2.y += xv * w2.y; a2.z += xv * w2.z; a2.w += xv * w2.w;
            a3.x += xv * w3.x; a3.y += xv * w3.y; a3.z += xv * w3.z; a3.w += xv * w3.w;
        }
    }
    if (nb + node < N) {
        float4* yo = (float4*)&Y[(nb + node) * 128 + j0];
        yo[0] = a0; yo[1] = a1; yo[2] = a2; yo[3] = a3;
    }
}

// ---------------- graph normalization + scatter ----------------
__global__ void deg_init(int N) {
    int i = blockIdx.x * blockDim.x + threadIdx.x;
    if (i < N) g_deg[i] = 1.0f;
}
__global__ void deg_scatter(const int* __restrict__ col, const float* __restrict__ ew, int E) {
    int e = blockIdx.x * blockDim.x + threadIdx.x;
    if (e < E) atomicAdd(&g_deg[col[e]], ew[e]);
}
__global__ void dinv_k(int N) {
    int i = blockIdx.x * blockDim.x + threadIdx.x;
    if (i < N) g_dinv[i] = rsqrtf(g_deg[i]);
}
__global__ void norm_k(const int* __restrict__ row, const int* __restrict__ col,
                       const float* __restrict__ ew, int E) {
    int e = blockIdx.x * blockDim.x + threadIdx.x;
    if (e < E) g_norm[e] = g_dinv[row[e]] * ew[e] * g_dinv[col[e]];
}
__global__ void self_init(const float* __restrict__ src, float* __restrict__ dst, int N) {
    int gid = blockIdx.x * blockDim.x + threadIdx.x;
    if (gid >= N * 32) return;
    int n = gid >> 5;
    float d = g_dinv[n];
    float s = d * d;
    float4 v = ((const float4*)src)[gid];
    v.x *= s; v.y *= s; v.z *= s; v.w *= s;
    ((float4*)dst)[gid] = v;
}
__global__ void scatter_k(const float* __restrict__ src, float* __restrict__ dst,
                          const int* __restrict__ row, const int* __restrict__ col, int E) {
    int gid = blockIdx.x * blockDim.x + threadIdx.x;
    int e = gid >> 5;
    if (e >= E) return;
    int lane = gid & 31;
    int r = row[e], cc = col[e];
    float nv = g_norm[e];
    float4 v = ((const float4*)(src + r * 128))[lane];
    float* d = dst + cc * 128 + lane * 4;
    atomicAdd(d + 0, nv * v.x);
    atomicAdd(d + 1, nv * v.y);
    atomicAdd(d + 2, nv * v.z);
    atomicAdd(d + 3, nv * v.w);
}
__global__ void bias_relu(float* __restrict__ h, const float* __restrict__ b, int N) {
    int gid = blockIdx.x * blockDim.x + threadIdx.x;
    if (gid < N * 128) h[gid] = fmaxf(h[gid] + b[gid & 127], 0.f);
}
__global__ void pool_k(const float* __restrict__ h, const float* __restrict__ b2,
                       float* __restrict__ out, int N) {
    int f = blockIdx.x;
    float s = 0.f;
    for (int n = threadIdx.x; n < N; n += blockDim.x) s += h[n * 128 + f];
    __shared__ float red[256];
    red[threadIdx.x] = s;
    __syncthreads();
    for (int o = 128; o > 0; o >>= 1) {
        if (threadIdx.x < o) red[threadIdx.x] += red[threadIdx.x + o];
        __syncthreads();
    }
    if (threadIdx.x == 0) out[f] = red[0] / (float)N + b2[f];
}

// ---------------- launch ----------------
extern "C" void kernel_launch(void* const* d_in, const int* in_sizes, int n_in,
                              void* d_out, int out_size) {
    const float* x   = (const float*)d_in[0];
    const int*   ei  = (const int*)d_in[1];
    const float* ew  = (const float*)d_in[2];
    const float* Wih = (const float*)d_in[3];
    const float* Whh = (const float*)d_in[4];
    const float* bih = (const float*)d_in[5];
    const float* bhh = (const float*)d_in[6];
    const float* W1  = (const float*)d_in[7];
    const float* b1  = (const float*)d_in[8];
    const float* W2  = (const float*)d_in[9];
    const float* b2  = (const float*)d_in[10];
    float* out = (float*)d_out;

    int N = in_sizes[0] / TT;
    int E = in_sizes[2];
    const int* row = ei;
    const int* col = ei + E;

    float *p_h1, *p_xw, *p_h2, *p_h3;
    cudaGetSymbolAddress((void**)&p_h1, g_h1);
    cudaGetSymbolAddress((void**)&p_xw, g_xw);
    cudaGetSymbolAddress((void**)&p_h2, g_h2);
    cudaGetSymbolAddress((void**)&p_h3, g_h3);

    cudaFuncSetAttribute(lstm_tc, cudaFuncAttributeMaxDynamicSharedMemorySize, SM_BYTES);

    int nb256 = (N + 255) / 256;
    int eb256 = (E + 255) / 256;

    prep_tc<<<(512 * 136 + 255) / 256, 256>>>(Whh, Wih, bih, bhh);
    xt_k<<<(TT * NN + 255) / 256, 256>>>(x);
    lstm_tc<<<NCTA, 256, SM_BYTES>>>();                // 125 CTAs -> g_h1 (relu'd)

    deg_init<<<nb256, 256>>>(N);
    deg_scatter<<<eb256, 256>>>(col, ew, E);
    dinv_k<<<nb256, 256>>>(N);
    norm_k<<<eb256, 256>>>(row, col, ew, E);

    // GCN layer 1
    gemm_k<<<(N + 31) / 32, 256>>>(p_h1, W1, p_xw, N);
    self_init<<<(N * 32 + 255) / 256, 256>>>(p_xw, p_h2, N);
    scatter_k<<<(E * 32 + 255) / 256, 256>>>(p_xw, p_h2, row, col, E);
    bias_relu<<<(N * 128 + 255) / 256, 256>>>(p_h2, b1, N);

    // GCN layer 2
    gemm_k<<<(N + 31) / 32, 256>>>(p_h2, W2, p_xw, N);
    self_init<<<(N * 32 + 255) / 256, 256>>>(p_xw, p_h3, N);
    scatter_k<<<(E * 32 + 255) / 256, 256>>>(p_xw, p_h3, row, col, E);

    pool_k<<<128, 256>>>(p_h3, b2, out, N);
}

// round 13
// speedup vs baseline: 3.4793x; 1.4324x over previous
#include <cuda_runtime.h>
#include <cuda_fp16.h>
#include <math.h>
#include <stdint.h>

#define NN 10000
#define TT 128
#define HH 128
#define EE 320000
#define MCTA 80          // nodes per CTA (125 * 80 = 10000 exactly)
#define NCTA 125
#define KT16 9           // K = 144 = 128 (h) + x + 1 + 14 pad, tiles of 16

// ---------------- device scratch ----------------
__device__ __align__(16) float g_h1[NN * HH];
__device__ __align__(16) float g_xw[NN * HH];
__device__ __align__(16) float g_h2[NN * HH];
__device__ __align__(16) float g_h3[NN * HH];
__device__ __align__(16) float g_deg[NN];
__device__ __align__(16) float g_dinv[NN];
__device__ __align__(16) float g_norm[EE];
__device__ __align__(16) float g_xT[TT * NN];       // transposed input (raw fp32)
// B fragment order, fp16 halves packed in words: [kt 9][nw 8][nt 8][lane 32][reg 2]
__device__ __align__(16) uint32_t g_Bhi[KT16 * 4096];
__device__ __align__(16) uint32_t g_Blo[KT16 * 4096];

// ---------------- helpers ----------------
__device__ __forceinline__ uint32_t smem_u32(const void* p) {
    uint32_t a;
    asm("{ .reg .u64 t; cvta.to.shared.u64 t, %1; cvt.u32.u64 %0, t; }" : "=r"(a) : "l"(p));
    return a;
}
__device__ __forceinline__ float ex2f(float x) { float r; asm("ex2.approx.f32 %0, %1;" : "=f"(r) : "f"(x)); return r; }
__device__ __forceinline__ float rcpf(float x) { float r; asm("rcp.approx.f32 %0, %1;" : "=f"(r) : "f"(x)); return r; }
__device__ __forceinline__ float sigf(float x) { return rcpf(1.0f + ex2f(-1.4426950408889634f * x)); }
__device__ __forceinline__ float tanhf_(float x) {
    float xc = fminf(fmaxf(x, -15.0f), 15.0f);
    float e = ex2f(2.8853900817779268f * xc);
    return (e - 1.0f) * rcpf(e + 1.0f);
}
// pack two fp32 -> half2 word (lo half = first arg = even-k element)
__device__ __forceinline__ uint32_t pack_h2(float a, float b) {
    uint32_t r;
    asm("{\n\t.reg .f16 l, h;\n\tcvt.rn.f16.f32 l, %1;\n\tcvt.rn.f16.f32 h, %2;\n\t"
        "mov.b32 %0, {l, h};\n\t}" : "=r"(r) : "f"(a), "f"(b));
    return r;
}
__device__ __forceinline__ void mma_f16(float& d0, float& d1, float& d2, float& d3,
                                        uint32_t a0, uint32_t a1, uint32_t a2, uint32_t a3,
                                        uint32_t b0, uint32_t b1) {
    asm volatile("mma.sync.aligned.m16n8k16.row.col.f32.f16.f16.f32 "
                 "{%0,%1,%2,%3}, {%4,%5,%6,%7}, {%8,%9}, {%0,%1,%2,%3};"
                 : "+f"(d0), "+f"(d1), "+f"(d2), "+f"(d3)
                 : "r"(a0), "r"(a1), "r"(a2), "r"(a3), "r"(b0), "r"(b1));
}
// ORDERED shared loads (R10 fix: never hoisted across cp.async waits / stores)
#define LDSV4(r0, r1, r2, r3, addr) \
    asm volatile("ld.shared.v4.b32 {%0,%1,%2,%3}, [%4];" \
        : "=r"(r0), "=r"(r1), "=r"(r2), "=r"(r3) : "r"(addr) : "memory")
#define LDSV2(r0, r1, addr) \
    asm volatile("ld.shared.v2.b32 {%0,%1}, [%2];" \
        : "=r"(r0), "=r"(r1) : "r"(addr) : "memory")

// ---------------- prep: B fragment-order, fp16 hi + lo ----------------
// D column d = gt*128 + jh. Warp nw owns jh in [nw*16, nw*16+16).
// nt = gt*2 + (jl/8), nlo = jl%8. B frag (m16n8k16 col-major):
//   (k,n): lane = n*4 + ((k&7)>>1), reg = (k&15)>>3, half = k&1, kt = k>>4.
// B rows: k<128: Whh[d][k]; k=128: Wih[d]; k=129: bih[d]+bhh[d]; else 0.
__global__ void prep_tc(const float* __restrict__ Whh, const float* __restrict__ Wih,
                        const float* __restrict__ bih, const float* __restrict__ bhh) {
    int idx = blockIdx.x * blockDim.x + threadIdx.x;
    if (idx >= 512 * 144) return;
    int d = idx / 144, k = idx % 144;
    float v;
    if (k < 128)       v = Whh[d * 128 + k];
    else if (k == 128) v = Wih[d];
    else if (k == 129) v = bih[d] + bhh[d];
    else               v = 0.0f;
    __half hi = __float2half_rn(v);
    float lo = v - __half2float(hi);
    __half lo_h = __float2half_rn(lo);
    int gt = d >> 7, jh = d & 127;
    int nw = jh >> 4, jl = jh & 15;
    int nt = gt * 2 + (jl >> 3), nlo = jl & 7;
    int kt = k >> 4, kk = k & 15;
    int lane = nlo * 4 + ((kk & 7) >> 1);
    int reg = kk >> 3, half = kk & 1;
    int hidx = (((((kt * 8) + nw) * 8 + nt) * 32 + lane) * 2 + reg) * 2 + half;
    ((__half*)g_Bhi)[hidx] = hi;
    ((__half*)g_Blo)[hidx] = lo_h;
}

__global__ void xt_k(const float* __restrict__ x) {
    int idx = blockIdx.x * blockDim.x + threadIdx.x;
    if (idx >= TT * NN) return;
    int t = idx / NN, n = idx % NN;
    g_xT[idx] = x[n * TT + t];
}

// ---------------- LSTM: 2-term fp16 mma.sync (AH·BH + AH·BL), ordered loads --------
// smem words: AH 5760 | BH 2x4096 | BL 2x4096 | CC 256*41 (floats)
#define AH_F   0
#define BH_F   5760
#define BL_F   13952
#define CC_F   22144
#define SMF    (22144 + 256 * 41)
#define SM_BYTES (SMF * 4)

__global__ __launch_bounds__(256, 1) void lstm_tc() {
    extern __shared__ __align__(16) float sm[];
    uint32_t* smw = (uint32_t*)sm;
    uint32_t sa = smem_u32(sm);
    int tid = threadIdx.x;
    int nw = tid >> 5;          // warp id = N-slice 0..7
    int lane = tid & 31;
    int nbase = blockIdx.x * MCTA;

    // zero all smem (A plane, BOTH B buffers, c)
    for (int i = tid; i < SMF; i += 256) sm[i] = 0.0f;
    __syncthreads();
    // x0 + ones packed word at kt=8, kk=0/1 (same word: half2(x, 1))
    if (tid < MCTA) {
        int n = tid, mt = n >> 4, r = n & 15;
        int lane0 = ((r & 7) << 2), reg0 = r >> 3;
        float xv = g_xT[0 * NN + nbase + n];
        smw[((mt * KT16 + 8) * 32 + lane0) * 4 + reg0] = pack_h2(xv, 1.0f);
    }
    __syncthreads();

    for (int t = 0; t < TT; t++) {
        float acc[8][5][4];
#pragma unroll
        for (int nt = 0; nt < 8; nt++)
#pragma unroll
            for (int mt = 0; mt < 5; mt++)
#pragma unroll
                for (int q = 0; q < 4; q++) acc[nt][mt][q] = 0.0f;

        // prefetch k-tile 0 (warp's hi + lo slices, 2KB each)
#pragma unroll
        for (int rr = 0; rr < 4; rr++) {
            uint32_t dh = sa + (uint32_t)((BH_F + nw * 512 + lane * 4 + rr * 128) * 4);
            const uint32_t* sh = g_Bhi + (0 * 4096 + nw * 512 + lane * 4 + rr * 128);
            asm volatile("cp.async.cg.shared.global [%0], [%1], 16;" :: "r"(dh), "l"(sh));
            uint32_t dl = sa + (uint32_t)((BL_F + nw * 512 + lane * 4 + rr * 128) * 4);
            const uint32_t* sl = g_Blo + (0 * 4096 + nw * 512 + lane * 4 + rr * 128);
            asm volatile("cp.async.cg.shared.global [%0], [%1], 16;" :: "r"(dl), "l"(sl));
        }
        asm volatile("cp.async.commit_group;" ::: "memory");

        for (int kt = 0; kt < KT16; kt++) {
            if (kt < KT16 - 1) {
                int nk = kt + 1;
                int off = (nk & 1) * 4096;
#pragma unroll
                for (int rr = 0; rr < 4; rr++) {
                    uint32_t dh = sa + (uint32_t)((BH_F + off + nw * 512 + lane * 4 + rr * 128) * 4);
                    const uint32_t* sh = g_Bhi + (nk * 4096 + nw * 512 + lane * 4 + rr * 128);
                    asm volatile("cp.async.cg.shared.global [%0], [%1], 16;" :: "r"(dh), "l"(sh));
                    uint32_t dl = sa + (uint32_t)((BL_F + off + nw * 512 + lane * 4 + rr * 128) * 4);
                    const uint32_t* sl = g_Blo + (nk * 4096 + nw * 512 + lane * 4 + rr * 128);
                    asm volatile("cp.async.cg.shared.global [%0], [%1], 16;" :: "r"(dl), "l"(sl));
                }
                asm volatile("cp.async.commit_group;" ::: "memory");
                asm volatile("cp.async.wait_group 1;" ::: "memory");
            } else {
                asm volatile("cp.async.wait_group 0;" ::: "memory");
            }
            __syncwarp();

            // B fragments (hi + lo) — ordered loads, cached for this k-tile
            uint32_t bh[8][2], bl[8][2];
            uint32_t bhib = sa + (uint32_t)((BH_F + (kt & 1) * 4096 + nw * 512) * 4);
            uint32_t blob = sa + (uint32_t)((BL_F + (kt & 1) * 4096 + nw * 512) * 4);
#pragma unroll
            for (int nt = 0; nt < 8; nt++) {
                LDSV2(bh[nt][0], bh[nt][1], bhib + (uint32_t)((nt * 32 + lane) * 8));
                LDSV2(bl[nt][0], bl[nt][1], blob + (uint32_t)((nt * 32 + lane) * 8));
            }
            // A frags streamed; 2 MMAs per (mt, nt)
#pragma unroll
            for (int mt = 0; mt < 5; mt++) {
                uint32_t a0, a1, a2, a3;
                uint32_t aaddr = sa + (uint32_t)((((mt * KT16 + kt) * 32 + lane) * 4) * 4);
                LDSV4(a0, a1, a2, a3, aaddr);
#pragma unroll
                for (int nt = 0; nt < 8; nt++) {
                    mma_f16(acc[nt][mt][0], acc[nt][mt][1], acc[nt][mt][2], acc[nt][mt][3],
                            a0, a1, a2, a3, bh[nt][0], bh[nt][1]);
                    mma_f16(acc[nt][mt][0], acc[nt][mt][1], acc[nt][mt][2], acc[nt][mt][3],
                            a0, a1, a2, a3, bl[nt][0], bl[nt][1]);
                }
            }
        }
        __syncthreads();   // all A reads done before epilogue overwrites A

        // epilogue: cell update; c in smem (stride 41, conflict-free)
#pragma unroll
        for (int mt = 0; mt < 5; mt++) {
#pragma unroll
            for (int rh = 0; rh < 2; rh++) {
                int r = (lane >> 2) + rh * 8;
                int n = mt * 16 + r;
#pragma unroll
                for (int jt = 0; jt < 2; jt++) {
                    float hv[2];
#pragma unroll
                    for (int nlo = 0; nlo < 2; nlo++) {
                        int ci = ((mt * 2 + rh) * 2 + jt) * 2 + nlo;
                        int q = rh * 2 + nlo;
                        float pi = acc[0 + jt][mt][q];
                        float pf = acc[2 + jt][mt][q];
                        float pg = acc[4 + jt][mt][q];
                        float po = acc[6 + jt][mt][q];
                        float cold = sm[CC_F + tid * 41 + ci];
                        float cn = sigf(pf) * cold + sigf(pi) * tanhf_(pg);
                        sm[CC_F + tid * 41 + ci] = cn;
                        float h = sigf(po) * tanhf_(cn);
                        hv[nlo] = h;
                        if (t == TT - 1 && nbase + n < NN) {
                            int jh = nw * 16 + jt * 8 + ((lane & 3) << 1) + nlo;
                            g_h1[(nbase + n) * HH + jh] = fmaxf(h, 0.0f);
                        }
                    }
                    // store packed h pair into A: kt tile = nw, kk = jt*8 + (lane&3)*2 + {0,1}
                    int lane2 = ((r & 7) << 2) + (lane & 3);
                    int reg2 = (r >> 3) + (jt << 1);
                    smw[((mt * KT16 + nw) * 32 + lane2) * 4 + reg2] = pack_h2(hv[0], hv[1]);
                }
            }
        }
        // x + ones word for next step
        if (t < TT - 1 && tid < MCTA) {
            int n = tid, mt = n >> 4, r = n & 15;
            int lane0 = ((r & 7) << 2), reg0 = r >> 3;
            float xv = g_xT[(t + 1) * NN + nbase + n];
            smw[((mt * KT16 + 8) * 32 + lane0) * 4 + reg0] = pack_h2(xv, 1.0f);
        }
        __syncthreads();
    }
}

// ---------------- GCN dense GEMM: Y[N,128] = X[N,128] @ W[128,128] ----------------
__global__ __launch_bounds__(256) void gemm_k(const float* __restrict__ X,
                                              const float* __restrict__ W,
                                              float* __restrict__ Y, int N) {
    __shared__ __align__(16) float Xs[32][128];
    __shared__ __align__(16) float Ws[64][128];
    int tid = threadIdx.x;
    int node = tid >> 3;
    int jq = tid & 7;
    int j0 = jq * 16;
    int nb = blockIdx.x * 32;

    for (int idx = tid; idx < 32 * 128; idx += 256) {
        int n = idx >> 7, k = idx & 127;
        Xs[n][k] = (nb + n < N) ? X[(nb + n) * 128 + k] : 0.f;
    }
    float4 a0 = make_float4(0.f, 0.f, 0.f, 0.f), a1 = a0, a2 = a0, a3 = a0;

    for (int half = 0; half < 2; half++) {
        __syncthreads();
        for (int idx = tid; idx < 64 * 128; idx += 256) {
            int k = idx >> 7, j = idx & 127;
            Ws[k][j] = W[(half * 64 + k) * 128 + j];
        }
        __syncthreads();
#pragma unroll 8
        for (int k8 = 0; k8 < 64; k8++) {
            float xv = Xs[node][half * 64 + k8];
            const float4* wr = (const float4*)&Ws[k8][j0];
            float4 w0 = wr[0], w1 = wr[1], w2 = wr[2], w3 = wr[3];
            a0.x += xv * w0.x; a0.y += xv * w0.y; a0.z += xv * w0.z; a0.w += xv * w0.w;
            a1.x += xv * w1.x; a1.y += xv * w1.y; a1.z += xv * w1.z; a1.w += xv * w1.w;
            a2.x += xv * w2.x; a2.y += xv * w2.y; a2.z += xv * w2.z; a2.w += xv * w2.w;
            a3.x += xv * w3.x; a3.y += xv * w3.y; a3.z += xv * w3.z; a3.w += xv * w3.w;
        }
    }
    if (nb + node < N) {
        float4* yo = (float4*)&Y[(nb + node) * 128 + j0];
        yo[0] = a0; yo[1] = a1; yo[2] = a2; yo[3] = a3;
    }
}

// ---------------- graph normalization + scatter ----------------
__global__ void deg_init(int N) {
    int i = blockIdx.x * blockDim.x + threadIdx.x;
    if (i < N) g_deg[i] = 1.0f;
}
__global__ void deg_scatter(const int* __restrict__ col, const float* __restrict__ ew, int E) {
    int e = blockIdx.x * blockDim.x + threadIdx.x;
    if (e < E) atomicAdd(&g_deg[col[e]], ew[e]);
}
__global__ void dinv_k(int N) {
    int i = blockIdx.x * blockDim.x + threadIdx.x;
    if (i < N) g_dinv[i] = rsqrtf(g_deg[i]);
}
__global__ void norm_k(const int* __restrict__ row, const int* __restrict__ col,
                       const float* __restrict__ ew, int E) {
    int e = blockIdx.x * blockDim.x + threadIdx.x;
    if (e < E) g_norm[e] = g_dinv[row[e]] * ew[e] * g_dinv[col[e]];
}
__global__ void self_init(const float* __restrict__ src, float* __restrict__ dst, int N) {
    int gid = blockIdx.x * blockDim.x + threadIdx.x;
    if (gid >= N * 32) return;
    int n = gid >> 5;
    float d = g_dinv[n];
    float s = d * d;
    float4 v = ((const float4*)src)[gid];
    v.x *= s; v.y *= s; v.z *= s; v.w *= s;
    ((float4*)dst)[gid] = v;
}
__global__ void scatter_k(const float* __restrict__ src, float* __restrict__ dst,
                          const int* __restrict__ row, const int* __restrict__ col, int E) {
    int gid = blockIdx.x * blockDim.x + threadIdx.x;
    int e = gid >> 5;
    if (e >= E) return;
    int lane = gid & 31;
    int r = row[e], cc = col[e];
    float nv = g_norm[e];
    float4 v = ((const float4*)(src + r * 128))[lane];
    float* d = dst + cc * 128 + lane * 4;
    atomicAdd(d + 0, nv * v.x);
    atomicAdd(d + 1, nv * v.y);
    atomicAdd(d + 2, nv * v.z);
    atomicAdd(d + 3, nv * v.w);
}
__global__ void bias_relu(float* __restrict__ h, const float* __restrict__ b, int N) {
    int gid = blockIdx.x * blockDim.x + threadIdx.x;
    if (gid < N * 128) h[gid] = fmaxf(h[gid] + b[gid & 127], 0.f);
}
__global__ void pool_k(const float* __restrict__ h, const float* __restrict__ b2,
                       float* __restrict__ out, int N) {
    int f = blockIdx.x;
    float s = 0.f;
    for (int n = threadIdx.x; n < N; n += blockDim.x) s += h[n * 128 + f];
    __shared__ float red[256];
    red[threadIdx.x] = s;
    __syncthreads();
    for (int o = 128; o > 0; o >>= 1) {
        if (threadIdx.x < o) red[threadIdx.x] += red[threadIdx.x + o];
        __syncthreads();
    }
    if (threadIdx.x == 0) out[f] = red[0] / (float)N + b2[f];
}

// ---------------- launch ----------------
extern "C" void kernel_launch(void* const* d_in, const int* in_sizes, int n_in,
                              void* d_out, int out_size) {
    const float* x   = (const float*)d_in[0];
    const int*   ei  = (const int*)d_in[1];
    const float* ew  = (const float*)d_in[2];
    const float* Wih = (const float*)d_in[3];
    const float* Whh = (const float*)d_in[4];
    const float* bih = (const float*)d_in[5];
    const float* bhh = (const float*)d_in[6];
    const float* W1  = (const float*)d_in[7];
    const float* b1  = (const float*)d_in[8];
    const float* W2  = (const float*)d_in[9];
    const float* b2  = (const float*)d_in[10];
    float* out = (float*)d_out;

    int N = in_sizes[0] / TT;
    int E = in_sizes[2];
    const int* row = ei;
    const int* col = ei + E;

    float *p_h1, *p_xw, *p_h2, *p_h3;
    cudaGetSymbolAddress((void**)&p_h1, g_h1);
    cudaGetSymbolAddress((void**)&p_xw, g_xw);
    cudaGetSymbolAddress((void**)&p_h2, g_h2);
    cudaGetSymbolAddress((void**)&p_h3, g_h3);

    cudaFuncSetAttribute(lstm_tc, cudaFuncAttributeMaxDynamicSharedMemorySize, SM_BYTES);

    int nb256 = (N + 255) / 256;
    int eb256 = (E + 255) / 256;

    prep_tc<<<(512 * 144 + 255) / 256, 256>>>(Whh, Wih, bih, bhh);
    xt_k<<<(TT * NN + 255) / 256, 256>>>(x);
    lstm_tc<<<NCTA, 256, SM_BYTES>>>();                // 125 CTAs -> g_h1 (relu'd)

    deg_init<<<nb256, 256>>>(N);
    deg_scatter<<<eb256, 256>>>(col, ew, E);
    dinv_k<<<nb256, 256>>>(N);
    norm_k<<<eb256, 256>>>(row, col, ew, E);

    // GCN layer 1
    gemm_k<<<(N + 31) / 32, 256>>>(p_h1, W1, p_xw, N);
    self_init<<<(N * 32 + 255) / 256, 256>>>(p_xw, p_h2, N);
    scatter_k<<<(E * 32 + 255) / 256, 256>>>(p_xw, p_h2, row, col, E);
    bias_relu<<<(N * 128 + 255) / 256, 256>>>(p_h2, b1, N);

    // GCN layer 2
    gemm_k<<<(N + 31) / 32, 256>>>(p_h2, W2, p_xw, N);
    self_init<<<(N * 32 + 255) / 256, 256>>>(p_xw, p_h3, N);
    scatter_k<<<(E * 32 + 255) / 256, 256>>>(p_xw, p_h3, row, col, E);

    pool_k<<<128, 256>>>(p_h3, b2, out, N);
}

// round 14
// speedup vs baseline: 4.3997x; 1.2645x over previous
#include <cuda_runtime.h>
#include <cuda_fp16.h>
#include <math.h>
#include <stdint.h>

#define NN 10000
#define TT 128
#define HH 128
#define EE 320000
#define MCTA 80          // nodes per CTA (125 * 80 = 10000 exactly)
#define NCTA 125
#define KT16 9           // K = 144 = 128 (h) + x + 1 + 14 pad, tiles of 16

// ---------------- device scratch ----------------
__device__ __align__(16) float g_h1[NN * HH];
__device__ __align__(16) float g_xw[NN * HH];
__device__ __align__(16) float g_h2[NN * HH];
__device__ __align__(16) float g_h3[NN * HH];
__device__ __align__(16) float g_deg[NN];
__device__ __align__(16) float g_dinv[NN];
__device__ __align__(16) float g_norm[EE];
__device__ __align__(16) float g_xT[TT * NN];       // transposed input (raw fp32)
// B fragment order, fp16 halves packed in words: [kt 9][nw 8][nt 8][lane 32][reg 2]
__device__ __align__(16) uint32_t g_Bhi[KT16 * 4096];
__device__ __align__(16) uint32_t g_Blo[KT16 * 4096];

// ---------------- helpers ----------------
__device__ __forceinline__ uint32_t smem_u32(const void* p) {
    uint32_t a;
    asm("{ .reg .u64 t; cvta.to.shared.u64 t, %1; cvt.u32.u64 %0, t; }" : "=r"(a) : "l"(p));
    return a;
}
// 1-MUFU nonlinearities (tanh.approx, sm_75+)
__device__ __forceinline__ float tanha(float x) {
    float r; asm("tanh.approx.f32 %0, %1;" : "=f"(r) : "f"(x)); return r;
}
__device__ __forceinline__ float siga(float x) {
    return fmaf(0.5f, tanha(0.5f * x), 0.5f);
}
// pack two fp32 -> half2 word (lo half = first arg = even-k element)
__device__ __forceinline__ uint32_t pack_h2(float a, float b) {
    uint32_t r;
    asm("{\n\t.reg .f16 l, h;\n\tcvt.rn.f16.f32 l, %1;\n\tcvt.rn.f16.f32 h, %2;\n\t"
        "mov.b32 %0, {l, h};\n\t}" : "=r"(r) : "f"(a), "f"(b));
    return r;
}
__device__ __forceinline__ void mma_f16(float& d0, float& d1, float& d2, float& d3,
                                        uint32_t a0, uint32_t a1, uint32_t a2, uint32_t a3,
                                        uint32_t b0, uint32_t b1) {
    asm volatile("mma.sync.aligned.m16n8k16.row.col.f32.f16.f16.f32 "
                 "{%0,%1,%2,%3}, {%4,%5,%6,%7}, {%8,%9}, {%0,%1,%2,%3};"
                 : "+f"(d0), "+f"(d1), "+f"(d2), "+f"(d3)
                 : "r"(a0), "r"(a1), "r"(a2), "r"(a3), "r"(b0), "r"(b1));
}
// ORDERED shared loads (R10 fix: never hoisted across cp.async waits / stores)
#define LDSV4(r0, r1, r2, r3, addr) \
    asm volatile("ld.shared.v4.b32 {%0,%1,%2,%3}, [%4];" \
        : "=r"(r0), "=r"(r1), "=r"(r2), "=r"(r3) : "r"(addr) : "memory")
#define LDSV2(r0, r1, addr) \
    asm volatile("ld.shared.v2.b32 {%0,%1}, [%2];" \
        : "=r"(r0), "=r"(r1) : "r"(addr) : "memory")

// ---------------- prep: B fragment-order, fp16 hi + lo ----------------
// D column d = gt*128 + jh. Warp nw owns jh in [nw*16, nw*16+16).
// nt = gt*2 + (jl/8), nlo = jl%8. B frag (m16n8k16 col-major):
//   (k,n): lane = n*4 + ((k&7)>>1), reg = (k&15)>>3, half = k&1, kt = k>>4.
// B rows: k<128: Whh[d][k]; k=128: Wih[d]; k=129: bih[d]+bhh[d]; else 0.
__global__ void prep_tc(const float* __restrict__ Whh, const float* __restrict__ Wih,
                        const float* __restrict__ bih, const float* __restrict__ bhh) {
    int idx = blockIdx.x * blockDim.x + threadIdx.x;
    if (idx >= 512 * 144) return;
    int d = idx / 144, k = idx % 144;
    float v;
    if (k < 128)       v = Whh[d * 128 + k];
    else if (k == 128) v = Wih[d];
    else if (k == 129) v = bih[d] + bhh[d];
    else               v = 0.0f;
    __half hi = __float2half_rn(v);
    float lo = v - __half2float(hi);
    __half lo_h = __float2half_rn(lo);
    int gt = d >> 7, jh = d & 127;
    int nw = jh >> 4, jl = jh & 15;
    int nt = gt * 2 + (jl >> 3), nlo = jl & 7;
    int kt = k >> 4, kk = k & 15;
    int lane = nlo * 4 + ((kk & 7) >> 1);
    int reg = kk >> 3, half = kk & 1;
    int hidx = (((((kt * 8) + nw) * 8 + nt) * 32 + lane) * 2 + reg) * 2 + half;
    ((__half*)g_Bhi)[hidx] = hi;
    ((__half*)g_Blo)[hidx] = lo_h;
}

__global__ void xt_k(const float* __restrict__ x) {
    int idx = blockIdx.x * blockDim.x + threadIdx.x;
    if (idx >= TT * NN) return;
    int t = idx / NN, n = idx % NN;
    g_xT[idx] = x[n * TT + t];
}

// ---------------- LSTM: 2-term fp16 mma, cyclic 3-stage B pipeline --------
// smem words: AH 5760 | BH 3x4096 | BL 3x4096 | CC 256*41 (floats)
#define AH_F   0
#define BH_F   5760
#define BL_F   18048
#define CC_F   30336
#define SMF    (30336 + 256 * 41)
#define SM_BYTES (SMF * 4)

// prefetch one k-tile (warp's hi + lo slices, 2KB each) into buffer bf
#define PREFETCH_TILE(tile, bf) do { \
    _Pragma("unroll") \
    for (int rr = 0; rr < 4; rr++) { \
        uint32_t dh = sa + (uint32_t)((BH_F + (bf) * 4096 + nw * 512 + lane * 4 + rr * 128) * 4); \
        const uint32_t* sh = g_Bhi + ((tile) * 4096 + nw * 512 + lane * 4 + rr * 128); \
        asm volatile("cp.async.cg.shared.global [%0], [%1], 16;" :: "r"(dh), "l"(sh)); \
        uint32_t dl = sa + (uint32_t)((BL_F + (bf) * 4096 + nw * 512 + lane * 4 + rr * 128) * 4); \
        const uint32_t* sl = g_Blo + ((tile) * 4096 + nw * 512 + lane * 4 + rr * 128); \
        asm volatile("cp.async.cg.shared.global [%0], [%1], 16;" :: "r"(dl), "l"(sl)); \
    } \
    asm volatile("cp.async.commit_group;" ::: "memory"); \
} while (0)

__global__ __launch_bounds__(256, 1) void lstm_tc() {
    extern __shared__ __align__(16) float sm[];
    uint32_t* smw = (uint32_t*)sm;
    uint32_t sa = smem_u32(sm);
    int tid = threadIdx.x;
    int nw = tid >> 5;          // warp id = N-slice 0..7
    int lane = tid & 31;
    int nbase = blockIdx.x * MCTA;

    // zero all smem (A plane, all B buffers, c)
    for (int i = tid; i < SMF; i += 256) sm[i] = 0.0f;
    __syncthreads();
    // x0 + ones packed word at kt=8, kk=0/1 (same word: half2(x, 1))
    if (tid < MCTA) {
        int n = tid, mt = n >> 4, r = n & 15;
        int lane0 = ((r & 7) << 2), reg0 = r >> 3;
        float xv = g_xT[0 * NN + nbase + n];
        smw[((mt * KT16 + 8) * 32 + lane0) * 4 + reg0] = pack_h2(xv, 1.0f);
    }
    __syncthreads();

    // pipeline prologue: tiles 0 and 1 in flight (buffers 0, 1)
    PREFETCH_TILE(0, 0);
    PREFETCH_TILE(1, 1);

    for (int t = 0; t < TT; t++) {
        float acc[8][5][4];
#pragma unroll
        for (int nt = 0; nt < 8; nt++)
#pragma unroll
            for (int mt = 0; mt < 5; mt++)
#pragma unroll
                for (int q = 0; q < 4; q++) acc[nt][mt][q] = 0.0f;

#pragma unroll
        for (int kt = 0; kt < KT16; kt++) {
            // cyclic prefetch: tile (kt+2) mod 9 -> buffer (kt+2) mod 3.
            // B is time-invariant, so this runs the pipeline across step
            // boundaries too (epilogue overlaps next step's early tiles).
            PREFETCH_TILE((kt + 2) % KT16, (kt + 2) % 3);
            asm volatile("cp.async.wait_group 2;" ::: "memory");
            __syncwarp();

            // B fragments (hi + lo) — ordered loads, cached for this k-tile
            uint32_t bh[8][2], bl[8][2];
            uint32_t bhib = sa + (uint32_t)((BH_F + (kt % 3) * 4096 + nw * 512) * 4);
            uint32_t blob = sa + (uint32_t)((BL_F + (kt % 3) * 4096 + nw * 512) * 4);
#pragma unroll
            for (int nt = 0; nt < 8; nt++) {
                LDSV2(bh[nt][0], bh[nt][1], bhib + (uint32_t)((nt * 32 + lane) * 8));
                LDSV2(bl[nt][0], bl[nt][1], blob + (uint32_t)((nt * 32 + lane) * 8));
            }
            // A frags streamed; 2 MMAs per (mt, nt)
#pragma unroll
            for (int mt = 0; mt < 5; mt++) {
                uint32_t a0, a1, a2, a3;
                uint32_t aaddr = sa + (uint32_t)((((mt * KT16 + kt) * 32 + lane) * 4) * 4);
                LDSV4(a0, a1, a2, a3, aaddr);
#pragma unroll
                for (int nt = 0; nt < 8; nt++) {
                    mma_f16(acc[nt][mt][0], acc[nt][mt][1], acc[nt][mt][2], acc[nt][mt][3],
                            a0, a1, a2, a3, bh[nt][0], bh[nt][1]);
                    mma_f16(acc[nt][mt][0], acc[nt][mt][1], acc[nt][mt][2], acc[nt][mt][3],
                            a0, a1, a2, a3, bl[nt][0], bl[nt][1]);
                }
            }
        }
        __syncthreads();   // all A reads done before epilogue overwrites A

        // epilogue: cell update; c in smem (stride 41, conflict-free)
#pragma unroll
        for (int mt = 0; mt < 5; mt++) {
#pragma unroll
            for (int rh = 0; rh < 2; rh++) {
                int r = (lane >> 2) + rh * 8;
                int n = mt * 16 + r;
#pragma unroll
                for (int jt = 0; jt < 2; jt++) {
                    float hv[2];
#pragma unroll
                    for (int nlo = 0; nlo < 2; nlo++) {
                        int ci = ((mt * 2 + rh) * 2 + jt) * 2 + nlo;
                        int q = rh * 2 + nlo;
                        float pi = acc[0 + jt][mt][q];
                        float pf = acc[2 + jt][mt][q];
                        float pg = acc[4 + jt][mt][q];
                        float po = acc[6 + jt][mt][q];
                        float cold = sm[CC_F + tid * 41 + ci];
                        float cn = siga(pf) * cold + siga(pi) * tanha(pg);
                        sm[CC_F + tid * 41 + ci] = cn;
                        float h = siga(po) * tanha(cn);
                        hv[nlo] = h;
                        if (t == TT - 1 && nbase + n < NN) {
                            int jh = nw * 16 + jt * 8 + ((lane & 3) << 1) + nlo;
                            g_h1[(nbase + n) * HH + jh] = fmaxf(h, 0.0f);
                        }
                    }
                    // store packed h pair into A: kt tile = nw, kk = jt*8 + (lane&3)*2 + {0,1}
                    int lane2 = ((r & 7) << 2) + (lane & 3);
                    int reg2 = (r >> 3) + (jt << 1);
                    smw[((mt * KT16 + nw) * 32 + lane2) * 4 + reg2] = pack_h2(hv[0], hv[1]);
                }
            }
        }
        // x + ones word for next step
        if (t < TT - 1 && tid < MCTA) {
            int n = tid, mt = n >> 4, r = n & 15;
            int lane0 = ((r & 7) << 2), reg0 = r >> 3;
            float xv = g_xT[(t + 1) * NN + nbase + n];
            smw[((mt * KT16 + 8) * 32 + lane0) * 4 + reg0] = pack_h2(xv, 1.0f);
        }
        __syncthreads();
    }
}

// ---------------- GCN dense GEMM: Y[N,128] = X[N,128] @ W[128,128] ----------------
__global__ __launch_bounds__(256) void gemm_k(const float* __restrict__ X,
                                              const float* __restrict__ W,
                                              float* __restrict__ Y, int N) {
    __shared__ __align__(16) float Xs[32][128];
    __shared__ __align__(16) float Ws[64][128];
    int tid = threadIdx.x;
    int node = tid >> 3;
    int jq = tid & 7;
    int j0 = jq * 16;
    int nb = blockIdx.x * 32;

    for (int idx = tid; idx < 32 * 128; idx += 256) {
        int n = idx >> 7, k = idx & 127;
        Xs[n][k] = (nb + n < N) ? X[(nb + n) * 128 + k] : 0.f;
    }
    float4 a0 = make_float4(0.f, 0.f, 0.f, 0.f), a1 = a0, a2 = a0, a3 = a0;

    for (int half = 0; half < 2; half++) {
        __syncthreads();
        for (int idx = tid; idx < 64 * 128; idx += 256) {
            int k = idx >> 7, j = idx & 127;
            Ws[k][j] = W[(half * 64 + k) * 128 + j];
        }
        __syncthreads();
#pragma unroll 8
        for (int k8 = 0; k8 < 64; k8++) {
            float xv = Xs[node][half * 64 + k8];
            const float4* wr = (const float4*)&Ws[k8][j0];
            float4 w0 = wr[0], w1 = wr[1], w2 = wr[2], w3 = wr[3];
            a0.x += xv * w0.x; a0.y += xv * w0.y; a0.z += xv * w0.z; a0.w += xv * w0.w;
            a1.x += xv * w1.x; a1.y += xv * w1.y; a1.z += xv * w1.z; a1.w += xv * w1.w;
            a2.x += xv * w2.x; a2.y += xv * w2.y; a2.z += xv * w2.z; a2.w += xv * w2.w;
            a3.x += xv * w3.x; a3.y += xv * w3.y; a3.z += xv * w3.z; a3.w += xv * w3.w;
        }
    }
    if (nb + node < N) {
        float4* yo = (float4*)&Y[(nb + node) * 128 + j0];
        yo[0] = a0; yo[1] = a1; yo[2] = a2; yo[3] = a3;
    }
}

// ---------------- graph normalization + scatter ----------------
__global__ void deg_init(int N) {
    int i = blockIdx.x * blockDim.x + threadIdx.x;
    if (i < N) g_deg[i] = 1.0f;
}
__global__ void deg_scatter(const int* __restrict__ col, const float* __restrict__ ew, int E) {
    int e = blockIdx.x * blockDim.x + threadIdx.x;
    if (e < E) atomicAdd(&g_deg[col[e]], ew[e]);
}
__global__ void dinv_k(int N) {
    int i = blockIdx.x * blockDim.x + threadIdx.x;
    if (i < N) g_dinv[i] = rsqrtf(g_deg[i]);
}
__global__ void norm_k(const int* __restrict__ row, const int* __restrict__ col,
                       const float* __restrict__ ew, int E) {
    int e = blockIdx.x * blockDim.x + threadIdx.x;
    if (e < E) g_norm[e] = g_dinv[row[e]] * ew[e] * g_dinv[col[e]];
}
__global__ void self_init(const float* __restrict__ src, float* __restrict__ dst, int N) {
    int gid = blockIdx.x * blockDim.x + threadIdx.x;
    if (gid >= N * 32) return;
    int n = gid >> 5;
    float d = g_dinv[n];
    float s = d * d;
    float4 v = ((const float4*)src)[gid];
    v.x *= s; v.y *= s; v.z *= s; v.w *= s;
    ((float4*)dst)[gid] = v;
}
__global__ void scatter_k(const float* __restrict__ src, float* __restrict__ dst,
                          const int* __restrict__ row, const int* __restrict__ col, int E) {
    int gid = blockIdx.x * blockDim.x + threadIdx.x;
    int e = gid >> 5;
    if (e >= E) return;
    int lane = gid & 31;
    int r = row[e], cc = col[e];
    float nv = g_norm[e];
    float4 v = ((const float4*)(src + r * 128))[lane];
    float* d = dst + cc * 128 + lane * 4;
    atomicAdd(d + 0, nv * v.x);
    atomicAdd(d + 1, nv * v.y);
    atomicAdd(d + 2, nv * v.z);
    atomicAdd(d + 3, nv * v.w);
}
__global__ void bias_relu(float* __restrict__ h, const float* __restrict__ b, int N) {
    int gid = blockIdx.x * blockDim.x + threadIdx.x;
    if (gid < N * 128) h[gid] = fmaxf(h[gid] + b[gid & 127], 0.f);
}
__global__ void pool_k(const float* __restrict__ h, const float* __restrict__ b2,
                       float* __restrict__ out, int N) {
    int f = blockIdx.x;
    float s = 0.f;
    for (int n = threadIdx.x; n < N; n += blockDim.x) s += h[n * 128 + f];
    __shared__ float red[256];
    red[threadIdx.x] = s;
    __syncthreads();
    for (int o = 128; o > 0; o >>= 1) {
        if (threadIdx.x < o) red[threadIdx.x] += red[threadIdx.x + o];
        __syncthreads();
    }
    if (threadIdx.x == 0) out[f] = red[0] / (float)N + b2[f];
}

// ---------------- launch ----------------
extern "C" void kernel_launch(void* const* d_in, const int* in_sizes, int n_in,
                              void* d_out, int out_size) {
    const float* x   = (const float*)d_in[0];
    const int*   ei  = (const int*)d_in[1];
    const float* ew  = (const float*)d_in[2];
    const float* Wih = (const float*)d_in[3];
    const float* Whh = (const float*)d_in[4];
    const float* bih = (const float*)d_in[5];
    const float* bhh = (const float*)d_in[6];
    const float* W1  = (const float*)d_in[7];
    const float* b1  = (const float*)d_in[8];
    const float* W2  = (const float*)d_in[9];
    const float* b2  = (const float*)d_in[10];
    float* out = (float*)d_out;

    int N = in_sizes[0] / TT;
    int E = in_sizes[2];
    const int* row = ei;
    const int* col = ei + E;

    float *p_h1, *p_xw, *p_h2, *p_h3;
    cudaGetSymbolAddress((void**)&p_h1, g_h1);
    cudaGetSymbolAddress((void**)&p_xw, g_xw);
    cudaGetSymbolAddress((void**)&p_h2, g_h2);
    cudaGetSymbolAddress((void**)&p_h3, g_h3);

    cudaFuncSetAttribute(lstm_tc, cudaFuncAttributeMaxDynamicSharedMemorySize, SM_BYTES);

    int nb256 = (N + 255) / 256;
    int eb256 = (E + 255) / 256;

    prep_tc<<<(512 * 144 + 255) / 256, 256>>>(Whh, Wih, bih, bhh);
    xt_k<<<(TT * NN + 255) / 256, 256>>>(x);
    lstm_tc<<<NCTA, 256, SM_BYTES>>>();                // 125 CTAs -> g_h1 (relu'd)

    deg_init<<<nb256, 256>>>(N);
    deg_scatter<<<eb256, 256>>>(col, ew, E);
    dinv_k<<<nb256, 256>>>(N);
    norm_k<<<eb256, 256>>>(row, col, ew, E);

    // GCN layer 1
    gemm_k<<<(N + 31) / 32, 256>>>(p_h1, W1, p_xw, N);
    self_init<<<(N * 32 + 255) / 256, 256>>>(p_xw, p_h2, N);
    scatter_k<<<(E * 32 + 255) / 256, 256>>>(p_xw, p_h2, row, col, E);
    bias_relu<<<(N * 128 + 255) / 256, 256>>>(p_h2, b1, N);

    // GCN layer 2
    gemm_k<<<(N + 31) / 32, 256>>>(p_h2, W2, p_xw, N);
    self_init<<<(N * 32 + 255) / 256, 256>>>(p_xw, p_h3, N);
    scatter_k<<<(E * 32 + 255) / 256, 256>>>(p_xw, p_h3, row, col, E);

    pool_k<<<128, 256>>>(p_h3, b2, out, N);
}

// round 15
// speedup vs baseline: 4.7665x; 1.0834x over previous
#include <cuda_runtime.h>
#include <cuda_fp16.h>
#include <math.h>
#include <stdint.h>

#define NN 10000
#define TT 128
#define HH 128
#define EE 320000
#define MCTA 80          // nodes per CTA (125 * 80 = 10000 exactly)
#define NCTA 125
#define KT16 9           // K = 144 = 128 (h) + x + 1 + 14 pad, tiles of 16

// ---------------- device scratch ----------------
__device__ __align__(16) float g_h1[NN * HH];
__device__ __align__(16) float g_xw[NN * HH];
__device__ __align__(16) float g_h2[NN * HH];
__device__ __align__(16) float g_h3[NN * HH];
__device__ __align__(16) float g_deg[NN];
__device__ __align__(16) float g_dinv[NN];
__device__ __align__(16) float g_norm[EE];
__device__ __align__(16) float g_xT[TT * NN];       // transposed input (raw fp32)
// B fragment order, fp16 halves packed in words: [kt 9][nw 8][nt 8][lane 32][reg 2]
__device__ __align__(16) uint32_t g_Bhi[KT16 * 4096];
__device__ __align__(16) uint32_t g_Blo[KT16 * 4096];

// ---------------- helpers ----------------
__device__ __forceinline__ uint32_t smem_u32(const void* p) {
    uint32_t a;
    asm("{ .reg .u64 t; cvta.to.shared.u64 t, %1; cvt.u32.u64 %0, t; }" : "=r"(a) : "l"(p));
    return a;
}
// 1-MUFU nonlinearities (tanh.approx, sm_75+)
__device__ __forceinline__ float tanha(float x) {
    float r; asm("tanh.approx.f32 %0, %1;" : "=f"(r) : "f"(x)); return r;
}
__device__ __forceinline__ float siga(float x) {
    return fmaf(0.5f, tanha(0.5f * x), 0.5f);
}
// pack two fp32 -> half2 word (lo half = first arg = even-k element)
__device__ __forceinline__ uint32_t pack_h2(float a, float b) {
    uint32_t r;
    asm("{\n\t.reg .f16 l, h;\n\tcvt.rn.f16.f32 l, %1;\n\tcvt.rn.f16.f32 h, %2;\n\t"
        "mov.b32 %0, {l, h};\n\t}" : "=r"(r) : "f"(a), "f"(b));
    return r;
}
__device__ __forceinline__ void mma_f16(float& d0, float& d1, float& d2, float& d3,
                                        uint32_t a0, uint32_t a1, uint32_t a2, uint32_t a3,
                                        uint32_t b0, uint32_t b1) {
    asm volatile("mma.sync.aligned.m16n8k16.row.col.f32.f16.f16.f32 "
                 "{%0,%1,%2,%3}, {%4,%5,%6,%7}, {%8,%9}, {%0,%1,%2,%3};"
                 : "+f"(d0), "+f"(d1), "+f"(d2), "+f"(d3)
                 : "r"(a0), "r"(a1), "r"(a2), "r"(a3), "r"(b0), "r"(b1));
}
// ORDERED shared loads (R10 fix: never hoisted across cp.async waits / stores)
#define LDSV4(r0, r1, r2, r3, addr) \
    asm volatile("ld.shared.v4.b32 {%0,%1,%2,%3}, [%4];" \
        : "=r"(r0), "=r"(r1), "=r"(r2), "=r"(r3) : "r"(addr) : "memory")
#define LDSV2(r0, r1, addr) \
    asm volatile("ld.shared.v2.b32 {%0,%1}, [%2];" \
        : "=r"(r0), "=r"(r1) : "r"(addr) : "memory")

// ---------------- prep: B fragment-order, fp16 hi + lo ----------------
// D column d = gt*128 + jh. Warp nw owns jh in [nw*16, nw*16+16).
// nt = gt*2 + (jl/8), nlo = jl%8. B frag (m16n8k16 col-major):
//   (k,n): lane = n*4 + ((k&7)>>1), reg = (k&15)>>3, half = k&1, kt = k>>4.
// B rows: k<128: Whh[d][k]; k=128: Wih[d]; k=129: bih[d]+bhh[d]; else 0.
__global__ void prep_tc(const float* __restrict__ Whh, const float* __restrict__ Wih,
                        const float* __restrict__ bih, const float* __restrict__ bhh) {
    int idx = blockIdx.x * blockDim.x + threadIdx.x;
    if (idx >= 512 * 144) return;
    int d = idx / 144, k = idx % 144;
    float v;
    if (k < 128)       v = Whh[d * 128 + k];
    else if (k == 128) v = Wih[d];
    else if (k == 129) v = bih[d] + bhh[d];
    else               v = 0.0f;
    __half hi = __float2half_rn(v);
    float lo = v - __half2float(hi);
    __half lo_h = __float2half_rn(lo);
    int gt = d >> 7, jh = d & 127;
    int nw = jh >> 4, jl = jh & 15;
    int nt = gt * 2 + (jl >> 3), nlo = jl & 7;
    int kt = k >> 4, kk = k & 15;
    int lane = nlo * 4 + ((kk & 7) >> 1);
    int reg = kk >> 3, half = kk & 1;
    int hidx = (((((kt * 8) + nw) * 8 + nt) * 32 + lane) * 2 + reg) * 2 + half;
    ((__half*)g_Bhi)[hidx] = hi;
    ((__half*)g_Blo)[hidx] = lo_h;
}

__global__ void xt_k(const float* __restrict__ x) {
    int idx = blockIdx.x * blockDim.x + threadIdx.x;
    if (idx >= TT * NN) return;
    int t = idx / NN, n = idx % NN;
    g_xT[idx] = x[n * TT + t];
}

// ---------------- LSTM: 2-term fp16 mma, cyclic 3-stage B pipeline --------
// smem words: AH 5760 | BH 3x4096 | BL 3x4096 | CC 256*41 (floats)
#define AH_F   0
#define BH_F   5760
#define BL_F   18048
#define CC_F   30336
#define SMF    (30336 + 256 * 41)
#define SM_BYTES (SMF * 4)

// prefetch one k-tile (warp's hi + lo slices, 2KB each) into buffer bf
#define PREFETCH_TILE(tile, bf) do { \
    _Pragma("unroll") \
    for (int rr = 0; rr < 4; rr++) { \
        uint32_t dh = sa + (uint32_t)((BH_F + (bf) * 4096 + nw * 512 + lane * 4 + rr * 128) * 4); \
        const uint32_t* sh = g_Bhi + ((tile) * 4096 + nw * 512 + lane * 4 + rr * 128); \
        asm volatile("cp.async.cg.shared.global [%0], [%1], 16;" :: "r"(dh), "l"(sh)); \
        uint32_t dl = sa + (uint32_t)((BL_F + (bf) * 4096 + nw * 512 + lane * 4 + rr * 128) * 4); \
        const uint32_t* sl = g_Blo + ((tile) * 4096 + nw * 512 + lane * 4 + rr * 128); \
        asm volatile("cp.async.cg.shared.global [%0], [%1], 16;" :: "r"(dl), "l"(sl)); \
    } \
    asm volatile("cp.async.commit_group;" ::: "memory"); \
} while (0)

__global__ __launch_bounds__(256, 1) void lstm_tc() {
    extern __shared__ __align__(16) float sm[];
    uint32_t* smw = (uint32_t*)sm;
    uint32_t sa = smem_u32(sm);
    int tid = threadIdx.x;
    int nw = tid >> 5;          // warp id = N-slice 0..7
    int lane = tid & 31;
    int nbase = blockIdx.x * MCTA;

    // zero all smem (A plane, all B buffers, c)
    for (int i = tid; i < SMF; i += 256) sm[i] = 0.0f;
    __syncthreads();
    // x0 + ones packed word at kt=8, kk=0/1 (same word: half2(x, 1))
    if (tid < MCTA) {
        int n = tid, mt = n >> 4, r = n & 15;
        int lane0 = ((r & 7) << 2), reg0 = r >> 3;
        float xv = g_xT[0 * NN + nbase + n];
        smw[((mt * KT16 + 8) * 32 + lane0) * 4 + reg0] = pack_h2(xv, 1.0f);
    }
    __syncthreads();

    // pipeline prologue: tiles 0 and 1 in flight (buffers 0, 1)
    PREFETCH_TILE(0, 0);
    PREFETCH_TILE(1, 1);

    for (int t = 0; t < TT; t++) {
        float acc[8][5][4];
#pragma unroll
        for (int nt = 0; nt < 8; nt++)
#pragma unroll
            for (int mt = 0; mt < 5; mt++)
#pragma unroll
                for (int q = 0; q < 4; q++) acc[nt][mt][q] = 0.0f;

#pragma unroll
        for (int kt = 0; kt < KT16; kt++) {
            // cyclic prefetch: tile (kt+2) mod 9 -> buffer (kt+2) mod 3.
            // B is time-invariant, so the pipeline runs across step
            // boundaries (epilogue overlaps next step's early tiles).
            PREFETCH_TILE((kt + 2) % KT16, (kt + 2) % 3);
            asm volatile("cp.async.wait_group 2;" ::: "memory");
            __syncwarp();

            // B fragments (hi + lo) — ordered loads, cached for this k-tile
            uint32_t bh[8][2], bl[8][2];
            uint32_t bhib = sa + (uint32_t)((BH_F + (kt % 3) * 4096 + nw * 512) * 4);
            uint32_t blob = sa + (uint32_t)((BL_F + (kt % 3) * 4096 + nw * 512) * 4);
#pragma unroll
            for (int nt = 0; nt < 8; nt++) {
                LDSV2(bh[nt][0], bh[nt][1], bhib + (uint32_t)((nt * 32 + lane) * 8));
                LDSV2(bl[nt][0], bl[nt][1], blob + (uint32_t)((nt * 32 + lane) * 8));
            }
            // A frags streamed; 2 MMAs per (mt, nt)
#pragma unroll
            for (int mt = 0; mt < 5; mt++) {
                uint32_t a0, a1, a2, a3;
                uint32_t aaddr = sa + (uint32_t)((((mt * KT16 + kt) * 32 + lane) * 4) * 4);
                LDSV4(a0, a1, a2, a3, aaddr);
#pragma unroll
                for (int nt = 0; nt < 8; nt++) {
                    mma_f16(acc[nt][mt][0], acc[nt][mt][1], acc[nt][mt][2], acc[nt][mt][3],
                            a0, a1, a2, a3, bh[nt][0], bh[nt][1]);
                    mma_f16(acc[nt][mt][0], acc[nt][mt][1], acc[nt][mt][2], acc[nt][mt][3],
                            a0, a1, a2, a3, bl[nt][0], bl[nt][1]);
                }
            }
        }
        __syncthreads();   // all A reads done before epilogue overwrites A

        // epilogue: cell update; c in smem (stride 41, conflict-free)
#pragma unroll
        for (int mt = 0; mt < 5; mt++) {
#pragma unroll
            for (int rh = 0; rh < 2; rh++) {
                int r = (lane >> 2) + rh * 8;
                int n = mt * 16 + r;
#pragma unroll
                for (int jt = 0; jt < 2; jt++) {
                    float hv[2];
#pragma unroll
                    for (int nlo = 0; nlo < 2; nlo++) {
                        int ci = ((mt * 2 + rh) * 2 + jt) * 2 + nlo;
                        int q = rh * 2 + nlo;
                        float pi = acc[0 + jt][mt][q];
                        float pf = acc[2 + jt][mt][q];
                        float pg = acc[4 + jt][mt][q];
                        float po = acc[6 + jt][mt][q];
                        float cold = sm[CC_F + tid * 41 + ci];
                        float cn = siga(pf) * cold + siga(pi) * tanha(pg);
                        sm[CC_F + tid * 41 + ci] = cn;
                        float h = siga(po) * tanha(cn);
                        hv[nlo] = h;
                        if (t == TT - 1 && nbase + n < NN) {
                            int jh = nw * 16 + jt * 8 + ((lane & 3) << 1) + nlo;
                            g_h1[(nbase + n) * HH + jh] = fmaxf(h, 0.0f);
                        }
                    }
                    // store packed h pair into A: kt tile = nw, kk = jt*8 + (lane&3)*2 + {0,1}
                    int lane2 = ((r & 7) << 2) + (lane & 3);
                    int reg2 = (r >> 3) + (jt << 1);
                    smw[((mt * KT16 + nw) * 32 + lane2) * 4 + reg2] = pack_h2(hv[0], hv[1]);
                }
            }
        }
        // x + ones word for next step
        if (t < TT - 1 && tid < MCTA) {
            int n = tid, mt = n >> 4, r = n & 15;
            int lane0 = ((r & 7) << 2), reg0 = r >> 3;
            float xv = g_xT[(t + 1) * NN + nbase + n];
            smw[((mt * KT16 + 8) * 32 + lane0) * 4 + reg0] = pack_h2(xv, 1.0f);
        }
        __syncthreads();
    }
}

// ---------------- GCN dense GEMM: Y[N,128] = X[N,128] @ W[128,128] ----------------
__global__ __launch_bounds__(256) void gemm_k(const float* __restrict__ X,
                                              const float* __restrict__ W,
                                              float* __restrict__ Y, int N) {
    __shared__ __align__(16) float Xs[32][128];
    __shared__ __align__(16) float Ws[64][128];
    int tid = threadIdx.x;
    int node = tid >> 3;
    int jq = tid & 7;
    int j0 = jq * 16;
    int nb = blockIdx.x * 32;

    for (int idx = tid; idx < 32 * 128; idx += 256) {
        int n = idx >> 7, k = idx & 127;
        Xs[n][k] = (nb + n < N) ? X[(nb + n) * 128 + k] : 0.f;
    }
    float4 a0 = make_float4(0.f, 0.f, 0.f, 0.f), a1 = a0, a2 = a0, a3 = a0;

    for (int half = 0; half < 2; half++) {
        __syncthreads();
        for (int idx = tid; idx < 64 * 128; idx += 256) {
            int k = idx >> 7, j = idx & 127;
            Ws[k][j] = W[(half * 64 + k) * 128 + j];
        }
        __syncthreads();
#pragma unroll 8
        for (int k8 = 0; k8 < 64; k8++) {
            float xv = Xs[node][half * 64 + k8];
            const float4* wr = (const float4*)&Ws[k8][j0];
            float4 w0 = wr[0], w1 = wr[1], w2 = wr[2], w3 = wr[3];
            a0.x += xv * w0.x; a0.y += xv * w0.y; a0.z += xv * w0.z; a0.w += xv * w0.w;
            a1.x += xv * w1.x; a1.y += xv * w1.y; a1.z += xv * w1.z; a1.w += xv * w1.w;
            a2.x += xv * w2.x; a2.y += xv * w2.y; a2.z += xv * w2.z; a2.w += xv * w2.w;
            a3.x += xv * w3.x; a3.y += xv * w3.y; a3.z += xv * w3.z; a3.w += xv * w3.w;
        }
    }
    if (nb + node < N) {
        float4* yo = (float4*)&Y[(nb + node) * 128 + j0];
        yo[0] = a0; yo[1] = a1; yo[2] = a2; yo[3] = a3;
    }
}

// ---------------- graph normalization + scatter ----------------
__global__ void deg_init(int N) {
    int i = blockIdx.x * blockDim.x + threadIdx.x;
    if (i < N) g_deg[i] = 1.0f;
}
__global__ void deg_scatter(const int* __restrict__ col, const float* __restrict__ ew, int E) {
    int e = blockIdx.x * blockDim.x + threadIdx.x;
    if (e < E) atomicAdd(&g_deg[col[e]], ew[e]);
}
__global__ void dinv_k(int N) {
    int i = blockIdx.x * blockDim.x + threadIdx.x;
    if (i < N) g_dinv[i] = rsqrtf(g_deg[i]);
}
__global__ void norm_k(const int* __restrict__ row, const int* __restrict__ col,
                       const float* __restrict__ ew, int E) {
    int e = blockIdx.x * blockDim.x + threadIdx.x;
    if (e < E) g_norm[e] = g_dinv[row[e]] * ew[e] * g_dinv[col[e]];
}
__global__ void self_init(const float* __restrict__ src, float* __restrict__ dst, int N) {
    int gid = blockIdx.x * blockDim.x + threadIdx.x;
    if (gid >= N * 32) return;
    int n = gid >> 5;
    float d = g_dinv[n];
    float s = d * d;
    float4 v = ((const float4*)src)[gid];
    v.x *= s; v.y *= s; v.z *= s; v.w *= s;
    ((float4*)dst)[gid] = v;
}
// warp per edge: dst[col] += norm[e] * src[row], one red.v4 per lane
__global__ void scatter_k(const float* __restrict__ src, float* __restrict__ dst,
                          const int* __restrict__ row, const int* __restrict__ col, int E) {
    int gid = blockIdx.x * blockDim.x + threadIdx.x;
    int e = gid >> 5;
    if (e >= E) return;
    int lane = gid & 31;
    int r = row[e], cc = col[e];
    float nv = g_norm[e];
    float4 v = ((const float4*)(src + r * 128))[lane];
    float* d = dst + cc * 128 + lane * 4;
    asm volatile("red.global.add.v4.f32 [%0], {%1, %2, %3, %4};"
                 :: "l"(d), "f"(nv * v.x), "f"(nv * v.y), "f"(nv * v.z), "f"(nv * v.w)
                 : "memory");
}
__global__ void bias_relu(float* __restrict__ h, const float* __restrict__ b, int N) {
    int gid = blockIdx.x * blockDim.x + threadIdx.x;
    if (gid < N * 128) h[gid] = fmaxf(h[gid] + b[gid & 127], 0.f);
}
__global__ void pool_k(const float* __restrict__ h, const float* __restrict__ b2,
                       float* __restrict__ out, int N) {
    int f = blockIdx.x;
    float s = 0.f;
    for (int n = threadIdx.x; n < N; n += blockDim.x) s += h[n * 128 + f];
    __shared__ float red[256];
    red[threadIdx.x] = s;
    __syncthreads();
    for (int o = 128; o > 0; o >>= 1) {
        if (threadIdx.x < o) red[threadIdx.x] += red[threadIdx.x + o];
        __syncthreads();
    }
    if (threadIdx.x == 0) out[f] = red[0] / (float)N + b2[f];
}

// ---------------- launch ----------------
extern "C" void kernel_launch(void* const* d_in, const int* in_sizes, int n_in,
                              void* d_out, int out_size) {
    const float* x   = (const float*)d_in[0];
    const int*   ei  = (const int*)d_in[1];
    const float* ew  = (const float*)d_in[2];
    const float* Wih = (const float*)d_in[3];
    const float* Whh = (const float*)d_in[4];
    const float* bih = (const float*)d_in[5];
    const float* bhh = (const float*)d_in[6];
    const float* W1  = (const float*)d_in[7];
    const float* b1  = (const float*)d_in[8];
    const float* W2  = (const float*)d_in[9];
    const float* b2  = (const float*)d_in[10];
    float* out = (float*)d_out;

    int N = in_sizes[0] / TT;
    int E = in_sizes[2];
    const int* row = ei;
    const int* col = ei + E;

    float *p_h1, *p_xw, *p_h2, *p_h3;
    cudaGetSymbolAddress((void**)&p_h1, g_h1);
    cudaGetSymbolAddress((void**)&p_xw, g_xw);
    cudaGetSymbolAddress((void**)&p_h2, g_h2);
    cudaGetSymbolAddress((void**)&p_h3, g_h3);

    cudaFuncSetAttribute(lstm_tc, cudaFuncAttributeMaxDynamicSharedMemorySize, SM_BYTES);

    int nb256 = (N + 255) / 256;
    int eb256 = (E + 255) / 256;

    prep_tc<<<(512 * 144 + 255) / 256, 256>>>(Whh, Wih, bih, bhh);
    xt_k<<<(TT * NN + 255) / 256, 256>>>(x);
    lstm_tc<<<NCTA, 256, SM_BYTES>>>();                // 125 CTAs -> g_h1 (relu'd)

    deg_init<<<nb256, 256>>>(N);
    deg_scatter<<<eb256, 256>>>(col, ew, E);
    dinv_k<<<nb256, 256>>>(N);
    norm_k<<<eb256, 256>>>(row, col, ew, E);

    // GCN layer 1
    gemm_k<<<(N + 31) / 32, 256>>>(p_h1, W1, p_xw, N);
    self_init<<<(N * 32 + 255) / 256, 256>>>(p_xw, p_h2, N);
    scatter_k<<<(E * 32 + 255) / 256, 256>>>(p_xw, p_h2, row, col, E);
    bias_relu<<<(N * 128 + 255) / 256, 256>>>(p_h2, b1, N);

    // GCN layer 2
    gemm_k<<<(N + 31) / 32, 256>>>(p_h2, W2, p_xw, N);
    self_init<<<(N * 32 + 255) / 256, 256>>>(p_xw, p_h3, N);
    scatter_k<<<(E * 32 + 255) / 256, 256>>>(p_xw, p_h3, row, col, E);

    pool_k<<<128, 256>>>(p_h3, b2, out, N);
}

// round 16
// speedup vs baseline: 4.7984x; 1.0067x over previous
#include <cuda_runtime.h>
#include <cuda_fp16.h>
#include <math.h>
#include <stdint.h>

#define NN 10000
#define TT 128
#define HH 128
#define EE 320000
#define MCTA 80          // nodes per CTA (125 * 80 = 10000 exactly)
#define NCTA 125
#define KT16 9           // K = 144 = 128 (h) + x + 1 + 14 pad, tiles of 16

// ---------------- device scratch ----------------
__device__ __align__(16) float g_h1[NN * HH];
__device__ __align__(16) float g_xw[NN * HH];
__device__ __align__(16) float g_h2[NN * HH];
__device__ __align__(16) float g_h3[NN * HH];
__device__ __align__(16) float g_deg[NN];
__device__ __align__(16) float g_dinv[NN];
__device__ __align__(16) float g_norm[EE];
__device__ __align__(16) float g_xT[TT * NN];       // transposed input (raw fp32)
// B fragment order, fp16 halves packed in words: [kt 9][nw 8][nt 8][lane 32][reg 2]
__device__ __align__(16) uint32_t g_Bhi[KT16 * 4096];
__device__ __align__(16) uint32_t g_Blo[KT16 * 4096];

// ---------------- helpers ----------------
__device__ __forceinline__ uint32_t smem_u32(const void* p) {
    uint32_t a;
    asm("{ .reg .u64 t; cvta.to.shared.u64 t, %1; cvt.u32.u64 %0, t; }" : "=r"(a) : "l"(p));
    return a;
}
// 1-MUFU nonlinearities (tanh.approx, sm_75+)
__device__ __forceinline__ float tanha(float x) {
    float r; asm("tanh.approx.f32 %0, %1;" : "=f"(r) : "f"(x)); return r;
}
__device__ __forceinline__ float siga(float x) {
    return fmaf(0.5f, tanha(0.5f * x), 0.5f);
}
// pack two fp32 -> half2 word (lo half = first arg = even-k element)
__device__ __forceinline__ uint32_t pack_h2(float a, float b) {
    uint32_t r;
    asm("{\n\t.reg .f16 l, h;\n\tcvt.rn.f16.f32 l, %1;\n\tcvt.rn.f16.f32 h, %2;\n\t"
        "mov.b32 %0, {l, h};\n\t}" : "=r"(r) : "f"(a), "f"(b));
    return r;
}
__device__ __forceinline__ void mma_f16(float& d0, float& d1, float& d2, float& d3,
                                        uint32_t a0, uint32_t a1, uint32_t a2, uint32_t a3,
                                        uint32_t b0, uint32_t b1) {
    asm volatile("mma.sync.aligned.m16n8k16.row.col.f32.f16.f16.f32 "
                 "{%0,%1,%2,%3}, {%4,%5,%6,%7}, {%8,%9}, {%0,%1,%2,%3};"
                 : "+f"(d0), "+f"(d1), "+f"(d2), "+f"(d3)
                 : "r"(a0), "r"(a1), "r"(a2), "r"(a3), "r"(b0), "r"(b1));
}
// ORDERED shared loads (R10 fix: never hoisted across cp.async waits / stores)
#define LDSV4(r0, r1, r2, r3, addr) \
    asm volatile("ld.shared.v4.b32 {%0,%1,%2,%3}, [%4];" \
        : "=r"(r0), "=r"(r1), "=r"(r2), "=r"(r3) : "r"(addr) : "memory")
#define LDSV2(r0, r1, addr) \
    asm volatile("ld.shared.v2.b32 {%0,%1}, [%2];" \
        : "=r"(r0), "=r"(r1) : "r"(addr) : "memory")

// ---------------- prep: B fragment-order, fp16 hi + lo ----------------
// D column d = gt*128 + jh. Warp nw owns jh in [nw*16, nw*16+16).
// nt = gt*2 + (jl/8), nlo = jl%8. B frag (m16n8k16 col-major):
//   (k,n): lane = n*4 + ((k&7)>>1), reg = (k&15)>>3, half = k&1, kt = k>>4.
// B rows: k<128: Whh[d][k]; k=128: Wih[d]; k=129: bih[d]+bhh[d]; else 0.
__global__ void prep_tc(const float* __restrict__ Whh, const float* __restrict__ Wih,
                        const float* __restrict__ bih, const float* __restrict__ bhh) {
    int idx = blockIdx.x * blockDim.x + threadIdx.x;
    if (idx >= 512 * 144) return;
    int d = idx / 144, k = idx % 144;
    float v;
    if (k < 128)       v = Whh[d * 128 + k];
    else if (k == 128) v = Wih[d];
    else if (k == 129) v = bih[d] + bhh[d];
    else               v = 0.0f;
    __half hi = __float2half_rn(v);
    float lo = v - __half2float(hi);
    __half lo_h = __float2half_rn(lo);
    int gt = d >> 7, jh = d & 127;
    int nw = jh >> 4, jl = jh & 15;
    int nt = gt * 2 + (jl >> 3), nlo = jl & 7;
    int kt = k >> 4, kk = k & 15;
    int lane = nlo * 4 + ((kk & 7) >> 1);
    int reg = kk >> 3, half = kk & 1;
    int hidx = (((((kt * 8) + nw) * 8 + nt) * 32 + lane) * 2 + reg) * 2 + half;
    ((__half*)g_Bhi)[hidx] = hi;
    ((__half*)g_Blo)[hidx] = lo_h;
}

// tiled transpose: x[n][t] -> g_xT[t][n], both sides coalesced
__global__ void xt_k(const float* __restrict__ x) {
    __shared__ float tile[32][33];
    int nb = blockIdx.x * 32;            // node base
    int tb = blockIdx.y * 32;            // time base
    int lx = threadIdx.x & 31;           // 0..31
    int ly4 = threadIdx.x >> 5;          // 0..7 (rows of 4)
    // read: node nb+ly4*4+rr, time tb+lx (coalesced in t)
#pragma unroll
    for (int rr = 0; rr < 4; rr++) {
        int n = nb + ly4 * 4 + rr;
        if (n < NN) tile[ly4 * 4 + rr][lx] = x[n * TT + tb + lx];
    }
    __syncthreads();
    // write: time tb+ly4*4+rr, node nb+lx (coalesced in n)
#pragma unroll
    for (int rr = 0; rr < 4; rr++) {
        int n = nb + lx;
        if (n < NN) g_xT[(tb + ly4 * 4 + rr) * NN + n] = tile[lx][ly4 * 4 + rr];
    }
}

// ---------------- LSTM: 2-term fp16 mma, cyclic 3-stage B pipeline --------
// smem words: AH 5760 | BH 3x4096 | BL 3x4096 | CC 256*41 (floats)
#define AH_F   0
#define BH_F   5760
#define BL_F   18048
#define CC_F   30336
#define SMF    (30336 + 256 * 41)
#define SM_BYTES (SMF * 4)

// prefetch one k-tile (warp's hi + lo slices, 2KB each) into buffer bf
#define PREFETCH_TILE(tile, bf) do { \
    _Pragma("unroll") \
    for (int rr = 0; rr < 4; rr++) { \
        uint32_t dh = sa + (uint32_t)((BH_F + (bf) * 4096 + nw * 512 + lane * 4 + rr * 128) * 4); \
        const uint32_t* sh = g_Bhi + ((tile) * 4096 + nw * 512 + lane * 4 + rr * 128); \
        asm volatile("cp.async.cg.shared.global [%0], [%1], 16;" :: "r"(dh), "l"(sh)); \
        uint32_t dl = sa + (uint32_t)((BL_F + (bf) * 4096 + nw * 512 + lane * 4 + rr * 128) * 4); \
        const uint32_t* sl = g_Blo + ((tile) * 4096 + nw * 512 + lane * 4 + rr * 128); \
        asm volatile("cp.async.cg.shared.global [%0], [%1], 16;" :: "r"(dl), "l"(sl)); \
    } \
    asm volatile("cp.async.commit_group;" ::: "memory"); \
} while (0)

__global__ __launch_bounds__(256, 1) void lstm_tc() {
    extern __shared__ __align__(16) float sm[];
    uint32_t* smw = (uint32_t*)sm;
    uint32_t sa = smem_u32(sm);
    int tid = threadIdx.x;
    int nw = tid >> 5;          // warp id = N-slice 0..7
    int lane = tid & 31;
    int nbase = blockIdx.x * MCTA;

    // zero all smem (A plane, all B buffers, c)
    for (int i = tid; i < SMF; i += 256) sm[i] = 0.0f;
    __syncthreads();
    // x0 + ones packed word at kt=8, kk=0/1 (same word: half2(x, 1))
    if (tid < MCTA) {
        int n = tid, mt = n >> 4, r = n & 15;
        int lane0 = ((r & 7) << 2), reg0 = r >> 3;
        float xv = g_xT[0 * NN + nbase + n];
        smw[((mt * KT16 + 8) * 32 + lane0) * 4 + reg0] = pack_h2(xv, 1.0f);
    }
    __syncthreads();

    // pipeline prologue: tiles 0 and 1 in flight (buffers 0, 1)
    PREFETCH_TILE(0, 0);
    PREFETCH_TILE(1, 1);

    for (int t = 0; t < TT; t++) {
        float acc[8][5][4];
#pragma unroll
        for (int nt = 0; nt < 8; nt++)
#pragma unroll
            for (int mt = 0; mt < 5; mt++)
#pragma unroll
                for (int q = 0; q < 4; q++) acc[nt][mt][q] = 0.0f;

#pragma unroll
        for (int kt = 0; kt < KT16; kt++) {
            // cyclic prefetch: tile (kt+2) mod 9 -> buffer (kt+2) mod 3.
            // B is time-invariant, so the pipeline runs across step
            // boundaries (epilogue overlaps next step's early tiles).
            PREFETCH_TILE((kt + 2) % KT16, (kt + 2) % 3);
            asm volatile("cp.async.wait_group 2;" ::: "memory");
            __syncwarp();

            // B fragments (hi + lo) — ordered loads, cached for this k-tile
            uint32_t bh[8][2], bl[8][2];
            uint32_t bhib = sa + (uint32_t)((BH_F + (kt % 3) * 4096 + nw * 512) * 4);
            uint32_t blob = sa + (uint32_t)((BL_F + (kt % 3) * 4096 + nw * 512) * 4);
#pragma unroll
            for (int nt = 0; nt < 8; nt++) {
                LDSV2(bh[nt][0], bh[nt][1], bhib + (uint32_t)((nt * 32 + lane) * 8));
                LDSV2(bl[nt][0], bl[nt][1], blob + (uint32_t)((nt * 32 + lane) * 8));
            }
            // A frags streamed; 2 MMAs per (mt, nt)
#pragma unroll
            for (int mt = 0; mt < 5; mt++) {
                uint32_t a0, a1, a2, a3;
                uint32_t aaddr = sa + (uint32_t)((((mt * KT16 + kt) * 32 + lane) * 4) * 4);
                LDSV4(a0, a1, a2, a3, aaddr);
#pragma unroll
                for (int nt = 0; nt < 8; nt++) {
                    mma_f16(acc[nt][mt][0], acc[nt][mt][1], acc[nt][mt][2], acc[nt][mt][3],
                            a0, a1, a2, a3, bh[nt][0], bh[nt][1]);
                    mma_f16(acc[nt][mt][0], acc[nt][mt][1], acc[nt][mt][2], acc[nt][mt][3],
                            a0, a1, a2, a3, bl[nt][0], bl[nt][1]);
                }
            }
        }
        __syncthreads();   // all A reads done before epilogue overwrites A

        // epilogue: cell update; c in smem (stride 41, conflict-free)
#pragma unroll
        for (int mt = 0; mt < 5; mt++) {
#pragma unroll
            for (int rh = 0; rh < 2; rh++) {
                int r = (lane >> 2) + rh * 8;
                int n = mt * 16 + r;
#pragma unroll
                for (int jt = 0; jt < 2; jt++) {
                    float hv[2];
#pragma unroll
                    for (int nlo = 0; nlo < 2; nlo++) {
                        int ci = ((mt * 2 + rh) * 2 + jt) * 2 + nlo;
                        int q = rh * 2 + nlo;
                        float pi = acc[0 + jt][mt][q];
                        float pf = acc[2 + jt][mt][q];
                        float pg = acc[4 + jt][mt][q];
                        float po = acc[6 + jt][mt][q];
                        float cold = sm[CC_F + tid * 41 + ci];
                        float cn = siga(pf) * cold + siga(pi) * tanha(pg);
                        sm[CC_F + tid * 41 + ci] = cn;
                        float h = siga(po) * tanha(cn);
                        hv[nlo] = h;
                        if (t == TT - 1 && nbase + n < NN) {
                            int jh = nw * 16 + jt * 8 + ((lane & 3) << 1) + nlo;
                            g_h1[(nbase + n) * HH + jh] = fmaxf(h, 0.0f);
                        }
                    }
                    // store packed h pair into A: kt tile = nw, kk = jt*8 + (lane&3)*2 + {0,1}
                    int lane2 = ((r & 7) << 2) + (lane & 3);
                    int reg2 = (r >> 3) + (jt << 1);
                    smw[((mt * KT16 + nw) * 32 + lane2) * 4 + reg2] = pack_h2(hv[0], hv[1]);
                }
            }
        }
        // x + ones word for next step
        if (t < TT - 1 && tid < MCTA) {
            int n = tid, mt = n >> 4, r = n & 15;
            int lane0 = ((r & 7) << 2), reg0 = r >> 3;
            float xv = g_xT[(t + 1) * NN + nbase + n];
            smw[((mt * KT16 + 8) * 32 + lane0) * 4 + reg0] = pack_h2(xv, 1.0f);
        }
        __syncthreads();
    }
}

// ---------------- GCN dense GEMM, fused:
// X' = bias ? relu(X + bias) : X  (bias fused into operand load)
// Y    = X' @ W                   (unscaled, for scatter source)
// Ydst = dinv[n]^2 * Y            (self-loop init of destination buffer)
__global__ __launch_bounds__(256) void gemm_k(const float* __restrict__ X,
                                              const float* __restrict__ W,
                                              float* __restrict__ Y,
                                              float* __restrict__ Ydst,
                                              const float* __restrict__ bias, int N) {
    __shared__ __align__(16) float Xs[32][128];
    __shared__ __align__(16) float Ws[64][128];
    int tid = threadIdx.x;
    int node = tid >> 3;
    int jq = tid & 7;
    int j0 = jq * 16;
    int nb = blockIdx.x * 32;

    for (int idx = tid; idx < 32 * 128; idx += 256) {
        int n = idx >> 7, k = idx & 127;
        float xv = (nb + n < N) ? X[(nb + n) * 128 + k] : 0.f;
        if (bias) xv = fmaxf(xv + bias[k], 0.f);
        Xs[n][k] = xv;
    }
    float4 a0 = make_float4(0.f, 0.f, 0.f, 0.f), a1 = a0, a2 = a0, a3 = a0;

    for (int half = 0; half < 2; half++) {
        __syncthreads();
        for (int idx = tid; idx < 64 * 128; idx += 256) {
            int k = idx >> 7, j = idx & 127;
            Ws[k][j] = W[(half * 64 + k) * 128 + j];
        }
        __syncthreads();
#pragma unroll 8
        for (int k8 = 0; k8 < 64; k8++) {
            float xv = Xs[node][half * 64 + k8];
            const float4* wr = (const float4*)&Ws[k8][j0];
            float4 w0 = wr[0], w1 = wr[1], w2 = wr[2], w3 = wr[3];
            a0.x += xv * w0.x; a0.y += xv * w0.y; a0.z += xv * w0.z; a0.w += xv * w0.w;
            a1.x += xv * w1.x; a1.y += xv * w1.y; a1.z += xv * w1.z; a1.w += xv * w1.w;
            a2.x += xv * w2.x; a2.y += xv * w2.y; a2.z += xv * w2.z; a2.w += xv * w2.w;
            a3.x += xv * w3.x; a3.y += xv * w3.y; a3.z += xv * w3.z; a3.w += xv * w3.w;
        }
    }
    if (nb + node < N) {
        float4* yo = (float4*)&Y[(nb + node) * 128 + j0];
        yo[0] = a0; yo[1] = a1; yo[2] = a2; yo[3] = a3;
        float dv = g_dinv[nb + node];
        float s = dv * dv;
        float4 b0 = make_float4(a0.x * s, a0.y * s, a0.z * s, a0.w * s);
        float4 b1v = make_float4(a1.x * s, a1.y * s, a1.z * s, a1.w * s);
        float4 b2v = make_float4(a2.x * s, a2.y * s, a2.z * s, a2.w * s);
        float4 b3v = make_float4(a3.x * s, a3.y * s, a3.z * s, a3.w * s);
        float4* yd = (float4*)&Ydst[(nb + node) * 128 + j0];
        yd[0] = b0; yd[1] = b1v; yd[2] = b2v; yd[3] = b3v;
    }
}

// ---------------- graph normalization + scatter ----------------
__global__ void deg_init(int N) {
    int i = blockIdx.x * blockDim.x + threadIdx.x;
    if (i < N) g_deg[i] = 1.0f;
}
__global__ void deg_scatter(const int* __restrict__ col, const float* __restrict__ ew, int E) {
    int e = blockIdx.x * blockDim.x + threadIdx.x;
    if (e < E) atomicAdd(&g_deg[col[e]], ew[e]);
}
__global__ void dinv_k(int N) {
    int i = blockIdx.x * blockDim.x + threadIdx.x;
    if (i < N) g_dinv[i] = rsqrtf(g_deg[i]);
}
__global__ void norm_k(const int* __restrict__ row, const int* __restrict__ col,
                       const float* __restrict__ ew, int E) {
    int e = blockIdx.x * blockDim.x + threadIdx.x;
    if (e < E) g_norm[e] = g_dinv[row[e]] * ew[e] * g_dinv[col[e]];
}
// warp per edge: dst[col] += norm[e] * src[row], one red.v4 per lane
__global__ void scatter_k(const float* __restrict__ src, float* __restrict__ dst,
                          const int* __restrict__ row, const int* __restrict__ col, int E) {
    int gid = blockIdx.x * blockDim.x + threadIdx.x;
    int e = gid >> 5;
    if (e >= E) return;
    int lane = gid & 31;
    int r = row[e], cc = col[e];
    float nv = g_norm[e];
    float4 v = ((const float4*)(src + r * 128))[lane];
    float* d = dst + cc * 128 + lane * 4;
    asm volatile("red.global.add.v4.f32 [%0], {%1, %2, %3, %4};"
                 :: "l"(d), "f"(nv * v.x), "f"(nv * v.y), "f"(nv * v.z), "f"(nv * v.w)
                 : "memory");
}
__global__ void pool_k(const float* __restrict__ h, const float* __restrict__ b2,
                       float* __restrict__ out, int N) {
    int f = blockIdx.x;
    float s = 0.f;
    for (int n = threadIdx.x; n < N; n += blockDim.x) s += h[n * 128 + f];
    __shared__ float red[256];
    red[threadIdx.x] = s;
    __syncthreads();
    for (int o = 128; o > 0; o >>= 1) {
        if (threadIdx.x < o) red[threadIdx.x] += red[threadIdx.x + o];
        __syncthreads();
    }
    if (threadIdx.x == 0) out[f] = red[0] / (float)N + b2[f];
}

// ---------------- launch ----------------
extern "C" void kernel_launch(void* const* d_in, const int* in_sizes, int n_in,
                              void* d_out, int out_size) {
    const float* x   = (const float*)d_in[0];
    const int*   ei  = (const int*)d_in[1];
    const float* ew  = (const float*)d_in[2];
    const float* Wih = (const float*)d_in[3];
    const float* Whh = (const float*)d_in[4];
    const float* bih = (const float*)d_in[5];
    const float* bhh = (const float*)d_in[6];
    const float* W1  = (const float*)d_in[7];
    const float* b1  = (const float*)d_in[8];
    const float* W2  = (const float*)d_in[9];
    const float* b2  = (const float*)d_in[10];
    float* out = (float*)d_out;

    int N = in_sizes[0] / TT;
    int E = in_sizes[2];
    const int* row = ei;
    const int* col = ei + E;

    float *p_h1, *p_xw, *p_h2, *p_h3;
    cudaGetSymbolAddress((void**)&p_h1, g_h1);
    cudaGetSymbolAddress((void**)&p_xw, g_xw);
    cudaGetSymbolAddress((void**)&p_h2, g_h2);
    cudaGetSymbolAddress((void**)&p_h3, g_h3);

    cudaFuncSetAttribute(lstm_tc, cudaFuncAttributeMaxDynamicSharedMemorySize, SM_BYTES);

    int nb256 = (N + 255) / 256;
    int eb256 = (E + 255) / 256;

    prep_tc<<<(512 * 144 + 255) / 256, 256>>>(Whh, Wih, bih, bhh);
    {
        dim3 tg((NN + 31) / 32, TT / 32);
        xt_k<<<tg, 256>>>(x);
    }
    lstm_tc<<<NCTA, 256, SM_BYTES>>>();                // 125 CTAs -> g_h1 (relu'd)

    deg_init<<<nb256, 256>>>(N);
    deg_scatter<<<eb256, 256>>>(col, ew, E);
    dinv_k<<<nb256, 256>>>(N);
    norm_k<<<eb256, 256>>>(row, col, ew, E);

    // GCN layer 1: gemm writes xw (unscaled) + h2 = dinv^2 * xw
    gemm_k<<<(N + 31) / 32, 256>>>(p_h1, W1, p_xw, p_h2, nullptr, N);
    scatter_k<<<(E * 32 + 255) / 256, 256>>>(p_xw, p_h2, row, col, E);

    // GCN layer 2: operand = relu(h2 + b1) fused into load
    gemm_k<<<(N + 31) / 32, 256>>>(p_h2, W2, p_xw, p_h3, b1, N);
    scatter_k<<<(E * 32 + 255) / 256, 256>>>(p_xw, p_h3, row, col, E);

    pool_k<<<128, 256>>>(p_h3, b2, out, N);
}